// round 12
// baseline (speedup 1.0000x reference)
#include <cuda_runtime.h>
#include <cuda_fp16.h>
#include <math.h>
#include <stdint.h>

// Problem constants
#define T_TOK 2048
#define C_DIM 1024
#define F_DIM 4096
#define E_NUM 8
#define ROUTER_BLOCKS 256   // 8 tokens (warps) per block

// Scratch (allocation-free rule: __device__ globals)
__device__ int   g_cnt[E_NUM];
__device__ int   g_idx[E_NUM * T_TOK];
__device__ float g_prob[T_TOK];
__device__ float g_partial[ROUTER_BLOCKS * E_NUM];
// fp16 operand planes
__device__ __align__(256) __half g_xh[(size_t)T_TOK * C_DIM];
__device__ __align__(256) __half g_xl[(size_t)T_TOK * C_DIM];
__device__ __align__(256) __half g_w1h[(size_t)E_NUM * C_DIM * F_DIM];
__device__ __align__(256) __half g_w2h[(size_t)E_NUM * F_DIM * C_DIM];
__device__ __align__(256) __half g_hh[(size_t)T_TOK * F_DIM];
__device__ __align__(256) __half g_hl[(size_t)T_TOK * F_DIM];

// ---------------------------------------------------------------------------
__global__ void init_kernel() {
    int i = threadIdx.x;
    if (i < E_NUM) g_cnt[i] = 0;
}

// Streaming converters ------------------------------------------------------
__global__ void cvt_w_kernel(const float4* __restrict__ w,
                             uint2* __restrict__ wh, int n4) {
    for (int i = blockIdx.x * blockDim.x + threadIdx.x; i < n4;
         i += gridDim.x * blockDim.x) {
        float4 f = w[i];
        __half2 a = __floats2half2_rn(f.x, f.y);
        __half2 b = __floats2half2_rn(f.z, f.w);
        wh[i] = make_uint2(*(uint32_t*)&a, *(uint32_t*)&b);
    }
}
__global__ void cvt_split_kernel(const float4* __restrict__ x,
                                 uint2* __restrict__ xh, uint2* __restrict__ xl,
                                 int n4) {
    for (int i = blockIdx.x * blockDim.x + threadIdx.x; i < n4;
         i += gridDim.x * blockDim.x) {
        float4 f = x[i];
        __half2 h01 = __floats2half2_rn(f.x, f.y);
        __half2 h23 = __floats2half2_rn(f.z, f.w);
        float rx = f.x - __low2float(h01);
        float ry = f.y - __high2float(h01);
        float rz = f.z - __low2float(h23);
        float rw = f.w - __high2float(h23);
        __half2 l01 = __floats2half2_rn(rx, ry);
        __half2 l23 = __floats2half2_rn(rz, rw);
        xh[i] = make_uint2(*(uint32_t*)&h01, *(uint32_t*)&h23);
        xl[i] = make_uint2(*(uint32_t*)&l01, *(uint32_t*)&l23);
    }
}

// ---------------------------------------------------------------------------
// Router: one warp per token. Deterministic importance partials per block.
__global__ void router_kernel(const float* __restrict__ x,
                              const float* __restrict__ rw,
                              const float* __restrict__ rb) {
    int warp = threadIdx.x >> 5;
    int lane = threadIdx.x & 31;
    int t = blockIdx.x * 8 + warp;

    float acc[E_NUM];
#pragma unroll
    for (int e = 0; e < E_NUM; e++) acc[e] = 0.f;

    const float* xr = x + (size_t)t * C_DIM;
    for (int c = lane; c < C_DIM; c += 32) {
        float xv = xr[c];
        const float4* r = (const float4*)(rw + c * E_NUM);
        float4 r0 = r[0];
        float4 r1 = r[1];
        acc[0] += xv * r0.x; acc[1] += xv * r0.y;
        acc[2] += xv * r0.z; acc[3] += xv * r0.w;
        acc[4] += xv * r1.x; acc[5] += xv * r1.y;
        acc[6] += xv * r1.z; acc[7] += xv * r1.w;
    }
#pragma unroll
    for (int e = 0; e < E_NUM; e++) {
#pragma unroll
        for (int o = 16; o > 0; o >>= 1)
            acc[e] += __shfl_xor_sync(0xffffffffu, acc[e], o);
    }

    __shared__ float s_p[8][E_NUM];
    if (lane == 0) {
        float lg[E_NUM];
        float mx = -1e30f; int am = 0;
#pragma unroll
        for (int e = 0; e < E_NUM; e++) {
            lg[e] = acc[e] + rb[e];
            if (lg[e] > mx) { mx = lg[e]; am = e; }
        }
        float s = 0.f, p[E_NUM];
#pragma unroll
        for (int e = 0; e < E_NUM; e++) { p[e] = expf(lg[e] - mx); s += p[e]; }
        float inv = 1.f / s;
#pragma unroll
        for (int e = 0; e < E_NUM; e++) { p[e] *= inv; s_p[warp][e] = p[e]; }
        g_prob[t] = p[am];
        int pos = atomicAdd(&g_cnt[am], 1);
        g_idx[am * T_TOK + pos] = t;
    }
    __syncthreads();
    if (threadIdx.x < E_NUM) {
        int e = threadIdx.x;
        float s = 0.f;
#pragma unroll
        for (int w = 0; w < 8; w++) s += s_p[w][e];
        g_partial[blockIdx.x * E_NUM + e] = s;
    }
}

// ---------------------------------------------------------------------------
// Aux loss: parallel deterministic reduction.
__global__ void aux_kernel(float* __restrict__ out, int out_size) {
    __shared__ float s_e[E_NUM];
    int wid = threadIdx.x >> 5;
    int lane = threadIdx.x & 31;
    if (wid < E_NUM) {
        float s = 0.f;
#pragma unroll
        for (int j = 0; j < ROUTER_BLOCKS / 32; j++)
            s += g_partial[(j * 32 + lane) * E_NUM + wid];
#pragma unroll
        for (int o = 16; o > 0; o >>= 1)
            s += __shfl_xor_sync(0xffffffffu, s, o);
        if (lane == 0) {
            float imp = s * (1.f / (float)T_TOK);
            float load = (float)g_cnt[wid] * (1.f / (float)T_TOK);
            s_e[wid] = imp * load;
        }
    }
    __syncthreads();
    if (threadIdx.x == 0) {
        float a = 0.f;
        for (int e = 0; e < E_NUM; e++) a += s_e[e];
        out[out_size - 1] = (float)E_NUM * a;
    }
}

// ===========================================================================
// fp16 2-term GEMM on pre-converted planes.  A = Ah + Al; B = Bh.
// D = Ah*Bh + Al*Bh (2 MMAs per k16). Warp tile 32x32; BKK=32;
// double-buffered SMEM, one barrier per K-iteration. Plain LDG/STS only.
// ===========================================================================
#define LDSM4(r, a) \
    asm volatile("ldmatrix.sync.aligned.m8n8.x4.shared.b16 {%0,%1,%2,%3}, [%4];" \
        : "=r"((r)[0]), "=r"((r)[1]), "=r"((r)[2]), "=r"((r)[3]) : "r"(a))
#define LDSM4T(r, a) \
    asm volatile("ldmatrix.sync.aligned.m8n8.x4.trans.shared.b16 {%0,%1,%2,%3}, [%4];" \
        : "=r"((r)[0]), "=r"((r)[1]), "=r"((r)[2]), "=r"((r)[3]) : "r"(a))
#define MMA16816(d, a, b0, b1) \
    asm volatile("mma.sync.aligned.m16n8k16.row.col.f32.f16.f16.f32 " \
        "{%0,%1,%2,%3}, {%4,%5,%6,%7}, {%8,%9}, {%0,%1,%2,%3};" \
        : "+f"((d)[0]), "+f"((d)[1]), "+f"((d)[2]), "+f"((d)[3]) \
        : "r"((a)[0]), "r"((a)[1]), "r"((a)[2]), "r"((a)[3]), "r"(b0), "r"(b1))

__device__ __forceinline__ uint32_t sptr(const void* p) {
    return (uint32_t)__cvta_generic_to_shared(p);
}

#define BKK 32
#define ASTR 40     // padded A row (32 + 8 fp16)

// FFN1: D = silu(x @ w1 + b1) -> (g_hh, g_hl); FFN2: D = (h @ w2 + b2)*prob -> Df
template<int K_TOTAL, int A_STRIDE, int B_STRIDE, bool FFN1,
         int BMT, int BNT, int NT, int MINB>
__global__ void __launch_bounds__(NT, MINB)
ffn_mma_kernel(const __half* __restrict__ Ah, const __half* __restrict__ Al,
               const __half* __restrict__ Bh, const float* __restrict__ bias,
               __half* __restrict__ Dh, __half* __restrict__ Dl,
               float* __restrict__ Df) {
    constexpr int BSTR = BNT + 8;
    constexpr int APL  = BMT * ASTR * 2;          // bytes per A plane
    constexpr int BSZ  = BKK * BSTR * 2;          // bytes per B plane
    constexpr int O_AHs = 0;
    constexpr int O_ALs = APL;
    constexpr int O_BHs = 2 * APL;
    constexpr int BUF_BYTES = 2 * APL + BSZ;
    constexpr int NWN  = BNT / 32;                // warps along N
    constexpr int TPRA = NT / BMT;                // threads per A row
    constexpr int ACH  = 32 / (8 * TPRA);         // 16B chunks/plane/thread
    constexpr int TPRB = NT / BKK;                // threads per B row
    constexpr int BCH  = BNT / (8 * TPRB);        // 16B chunks/thread

    const int e = blockIdx.y;
    const int cnt = g_cnt[e];
    const int m0 = blockIdx.z * BMT;
    if (m0 >= cnt) return;
    const int n0 = blockIdx.x * BNT;

    extern __shared__ __align__(16) char dsm[];
    __shared__ int toks_s[BMT];

    const int tid = threadIdx.x;
    const int wid = tid >> 5;
    const int lane = tid & 31;
    const int warp_m = wid / NWN;
    const int warp_n = wid % NWN;

    if (tid < BMT) {
        int m = m0 + tid;
        toks_s[tid] = (m < cnt) ? g_idx[e * T_TOK + m] : -1;
    }
    __syncthreads();

    // loader mapping (invalid rows read token 0; outputs skipped in epilogue)
    const int a_row = tid / TPRA;
    const int a_c   = (tid % TPRA) * ACH;         // 8-half chunk idx within row
    const int tokA  = toks_s[a_row];
    const __half* aSrcH = Ah + (size_t)((tokA >= 0) ? tokA : 0) * A_STRIDE;
    const __half* aSrcL = Al + (size_t)((tokA >= 0) ? tokA : 0) * A_STRIDE;
    const int b_row = tid / TPRB;
    const int b_c   = (tid % TPRB) * BCH;
    const __half* bSrc = Bh + (size_t)e * K_TOTAL * B_STRIDE
                        + (size_t)b_row * B_STRIDE + n0 + b_c * 8;

    const uint32_t a_sts = (uint32_t)((a_row * ASTR + a_c * 8) * 2);
    const uint32_t b_sts = (uint32_t)((b_row * BSTR + b_c * 8) * 2);

    uint4 rah[ACH], ral[ACH], rbv[BCH];
#define LDG_TILE(k0) do { \
    _Pragma("unroll") \
    for (int j = 0; j < ACH; j++) { \
        rah[j] = *(const uint4*)(aSrcH + (k0) + (a_c + j) * 8); \
        ral[j] = *(const uint4*)(aSrcL + (k0) + (a_c + j) * 8); \
    } \
    _Pragma("unroll") \
    for (int j = 0; j < BCH; j++) \
        rbv[j] = *(const uint4*)(bSrc + (size_t)(k0) * B_STRIDE + j * 8); \
} while (0)
#define STS_TILE(base) do { \
    _Pragma("unroll") \
    for (int j = 0; j < ACH; j++) { \
        *(uint4*)((base) + O_AHs + a_sts + j * 16) = rah[j]; \
        *(uint4*)((base) + O_ALs + a_sts + j * 16) = ral[j]; \
    } \
    _Pragma("unroll") \
    for (int j = 0; j < BCH; j++) \
        *(uint4*)((base) + O_BHs + b_sts + j * 16) = rbv[j]; \
} while (0)

    // prologue: iter 0 -> buffer 0, prefetch iter 1
    LDG_TILE(0);
    STS_TILE(dsm);
    if (K_TOTAL > BKK) LDG_TILE(BKK);
    __syncthreads();

    float acc[2][4][4];
#pragma unroll
    for (int mi = 0; mi < 2; mi++)
#pragma unroll
        for (int nj = 0; nj < 4; nj++)
#pragma unroll
            for (int q = 0; q < 4; q++) acc[mi][nj][q] = 0.f;

    const uint32_t dynb = sptr(dsm);
    const int lm  = lane & 15;
    const int lg8 = (lane >> 4) * 8;
    const uint32_t aoff = (uint32_t)(((warp_m * 32 + lm) * ASTR + lg8) * 2);
    const uint32_t boff = (uint32_t)((lm * BSTR + warp_n * 32 + lg8) * 2);

    const int n_iters = K_TOTAL / BKK;
    for (int it = 0; it < n_iters; ++it) {
        const int cur = it & 1;

        // STS iter it+1 into the other buffer (its readers finished last iter)
        if (it + 1 < n_iters) {
            char* nb = dsm + (cur ^ 1) * BUF_BYTES;
            STS_TILE(nb);
        }
        // LDG iter it+2 into registers
        if (it + 2 < n_iters) LDG_TILE((it + 2) * BKK);

        // compute current buffer: 2 x k16 steps, 2-term fp16 split
        const uint32_t sb = dynb + cur * BUF_BYTES;
        const uint32_t aH = sb + O_AHs;
        const uint32_t aL = sb + O_ALs;
        const uint32_t bB = sb + O_BHs;
#pragma unroll
        for (int kk = 0; kk < 2; kk++) {
            uint32_t fah[2][4], fal[2][4], fbh[2][4];
#pragma unroll
            for (int ni = 0; ni < 2; ni++) {
                uint32_t ba = boff + (uint32_t)((kk * 16 * BSTR + ni * 16) * 2);
                LDSM4T(fbh[ni], bB + ba);
            }
#pragma unroll
            for (int mi = 0; mi < 2; mi++) {
                uint32_t aa = aoff + (uint32_t)((mi * 16 * ASTR + kk * 16) * 2);
                LDSM4(fah[mi], aH + aa);
                LDSM4(fal[mi], aL + aa);
            }
#pragma unroll
            for (int mi = 0; mi < 2; mi++) {
#pragma unroll
                for (int nj = 0; nj < 4; nj++) {
                    uint32_t b0 = fbh[nj >> 1][(nj & 1) * 2];
                    uint32_t b1 = fbh[nj >> 1][(nj & 1) * 2 + 1];
                    MMA16816(acc[mi][nj], fah[mi], b0, b1);
                    MMA16816(acc[mi][nj], fal[mi], b0, b1);
                }
            }
        }
        __syncthreads();
    }
#undef LDG_TILE
#undef STS_TILE

    // epilogue: straight from registers
    const int r4 = lane >> 2;
    const int c2 = (lane & 3) * 2;
    const float* bias_p = bias + (size_t)e * B_STRIDE + n0 + warp_n * 32;
#pragma unroll
    for (int mi = 0; mi < 2; mi++) {
#pragma unroll
        for (int half_ = 0; half_ < 2; half_++) {
            int rl = warp_m * 32 + mi * 16 + half_ * 8 + r4;
            int tok = toks_s[rl];
            if (tok < 0) continue;
#pragma unroll
            for (int nj = 0; nj < 4; nj++) {
                int c = nj * 8 + c2;
                float v0 = acc[mi][nj][half_ * 2 + 0] + bias_p[c];
                float v1 = acc[mi][nj][half_ * 2 + 1] + bias_p[c + 1];
                if (FFN1) {
                    v0 = v0 / (1.f + expf(-v0));
                    v1 = v1 / (1.f + expf(-v1));
                    __half h0 = __float2half_rn(v0);
                    __half h1 = __float2half_rn(v1);
                    __half l0 = __float2half_rn(v0 - __half2float(h0));
                    __half l1 = __float2half_rn(v1 - __half2float(h1));
                    size_t o = (size_t)tok * B_STRIDE + n0 + warp_n * 32 + c;
                    *(__half2*)(Dh + o) = __halves2half2(h0, h1);
                    *(__half2*)(Dl + o) = __halves2half2(l0, l1);
                } else {
                    float p = g_prob[tok];
                    float2 o2;
                    o2.x = v0 * p;
                    o2.y = v1 * p;
                    *(float2*)(Df + (size_t)tok * B_STRIDE + n0 + warp_n * 32 + c) = o2;
                }
            }
        }
    }
}

// ---------------------------------------------------------------------------
// FFN1: BM=128, BN=128, 512 threads. FFN2: BM=64, BN=64, 128 threads.
#define F1_SMEM (2 * (2 * (128 * ASTR * 2) + (BKK * (128 + 8) * 2)))   // 58368
#define F2_SMEM (2 * (2 * (64 * ASTR * 2) + (BKK * (64 + 8) * 2)))     // 29696

extern "C" void kernel_launch(void* const* d_in, const int* in_sizes, int n_in,
                              void* d_out, int out_size) {
    const float* x  = (const float*)d_in[0];
    const float* rw = (const float*)d_in[1];
    const float* rb = (const float*)d_in[2];
    const float* w1 = (const float*)d_in[3];
    const float* b1 = (const float*)d_in[4];
    const float* w2 = (const float*)d_in[5];
    const float* b2 = (const float*)d_in[6];
    float* out = (float*)d_out;

    cudaFuncSetAttribute(
        ffn_mma_kernel<C_DIM, C_DIM, F_DIM, true, 128, 128, 512, 1>,
        cudaFuncAttributeMaxDynamicSharedMemorySize, F1_SMEM);
    cudaFuncSetAttribute(
        ffn_mma_kernel<F_DIM, F_DIM, C_DIM, false, 64, 64, 128, 2>,
        cudaFuncAttributeMaxDynamicSharedMemorySize, F2_SMEM);

    __half *xh, *xl, *w1h, *w2h, *hh, *hl;
    cudaGetSymbolAddress((void**)&xh,  g_xh);
    cudaGetSymbolAddress((void**)&xl,  g_xl);
    cudaGetSymbolAddress((void**)&w1h, g_w1h);
    cudaGetSymbolAddress((void**)&w2h, g_w2h);
    cudaGetSymbolAddress((void**)&hh,  g_hh);
    cudaGetSymbolAddress((void**)&hl,  g_hl);

    init_kernel<<<1, 32>>>();
    // operand prep (streaming)
    const int n4w = E_NUM * C_DIM * F_DIM / 4;
    cvt_w_kernel<<<1184, 256>>>((const float4*)w1, (uint2*)w1h, n4w);
    cvt_w_kernel<<<1184, 256>>>((const float4*)w2, (uint2*)w2h, n4w);
    cvt_split_kernel<<<512, 256>>>((const float4*)x, (uint2*)xh, (uint2*)xl,
                                   T_TOK * C_DIM / 4);
    router_kernel<<<ROUTER_BLOCKS, 256>>>(x, rw, rb);
    aux_kernel<<<1, 256>>>(out, out_size);

    // FFN1: [cnt_e,1024] @ [1024,4096] -> silu -> (g_hh, g_hl)
    ffn_mma_kernel<C_DIM, C_DIM, F_DIM, true, 128, 128, 512, 1>
        <<<dim3(F_DIM / 128, E_NUM, T_TOK / 128), 512, F1_SMEM>>>(
            xh, xl, w1h, b1, hh, hl, nullptr);
    // FFN2: [cnt_e,4096] @ [4096,1024] -> *prob -> out
    ffn_mma_kernel<F_DIM, F_DIM, C_DIM, false, 64, 64, 128, 2>
        <<<dim3(C_DIM / 64, E_NUM, T_TOK / 64), 128, F2_SMEM>>>(
            hh, hl, w2h, b2, nullptr, nullptr, out);
}

// round 13
// speedup vs baseline: 1.0132x; 1.0132x over previous
#include <cuda_runtime.h>
#include <cuda_fp16.h>
#include <math.h>
#include <stdint.h>

// Problem constants
#define T_TOK 2048
#define C_DIM 1024
#define F_DIM 4096
#define E_NUM 8
#define ROUTER_BLOCKS 256   // 8 tokens (warps) per block

// Scratch (allocation-free rule: __device__ globals)
__device__ int   g_cnt[E_NUM];
__device__ int   g_idx[E_NUM * T_TOK];
__device__ float g_prob[T_TOK];
__device__ float g_partial[ROUTER_BLOCKS * E_NUM];
// fp16 operand planes
__device__ __align__(256) __half g_xh[(size_t)T_TOK * C_DIM];
__device__ __align__(256) __half g_xl[(size_t)T_TOK * C_DIM];
__device__ __align__(256) __half g_w1h[(size_t)E_NUM * C_DIM * F_DIM];
__device__ __align__(256) __half g_w2h[(size_t)E_NUM * F_DIM * C_DIM];
__device__ __align__(256) __half g_hh[(size_t)T_TOK * F_DIM];
__device__ __align__(256) __half g_hl[(size_t)T_TOK * F_DIM];

// ---------------------------------------------------------------------------
__global__ void init_kernel() {
    int i = threadIdx.x;
    if (i < E_NUM) g_cnt[i] = 0;
}

// Streaming converters (ILP-4, streaming loads/stores) ----------------------
__global__ void cvt_w_kernel(const float4* __restrict__ w,
                             uint2* __restrict__ wh, int n4) {
    const int stride = gridDim.x * blockDim.x;
    const int i0 = blockIdx.x * blockDim.x + threadIdx.x;
    for (int base = i0; base < n4; base += 4 * stride) {
        float4 f[4];
#pragma unroll
        for (int j = 0; j < 4; j++) {
            int i = base + j * stride;
            if (i < n4) f[j] = __ldcs(&w[i]);
        }
#pragma unroll
        for (int j = 0; j < 4; j++) {
            int i = base + j * stride;
            if (i < n4) {
                __half2 a = __floats2half2_rn(f[j].x, f[j].y);
                __half2 b = __floats2half2_rn(f[j].z, f[j].w);
                __stcs(&wh[i], make_uint2(*(uint32_t*)&a, *(uint32_t*)&b));
            }
        }
    }
}
__global__ void cvt_split_kernel(const float4* __restrict__ x,
                                 uint2* __restrict__ xh, uint2* __restrict__ xl,
                                 int n4) {
    const int stride = gridDim.x * blockDim.x;
    const int i0 = blockIdx.x * blockDim.x + threadIdx.x;
    for (int base = i0; base < n4; base += 4 * stride) {
        float4 f[4];
#pragma unroll
        for (int j = 0; j < 4; j++) {
            int i = base + j * stride;
            if (i < n4) f[j] = __ldcs(&x[i]);
        }
#pragma unroll
        for (int j = 0; j < 4; j++) {
            int i = base + j * stride;
            if (i < n4) {
                __half2 h01 = __floats2half2_rn(f[j].x, f[j].y);
                __half2 h23 = __floats2half2_rn(f[j].z, f[j].w);
                float rx = f[j].x - __low2float(h01);
                float ry = f[j].y - __high2float(h01);
                float rz = f[j].z - __low2float(h23);
                float rw = f[j].w - __high2float(h23);
                __half2 l01 = __floats2half2_rn(rx, ry);
                __half2 l23 = __floats2half2_rn(rz, rw);
                __stcs(&xh[i], make_uint2(*(uint32_t*)&h01, *(uint32_t*)&h23));
                __stcs(&xl[i], make_uint2(*(uint32_t*)&l01, *(uint32_t*)&l23));
            }
        }
    }
}

// ---------------------------------------------------------------------------
// Router: one warp per token. Deterministic importance partials per block.
__global__ void router_kernel(const float* __restrict__ x,
                              const float* __restrict__ rw,
                              const float* __restrict__ rb) {
    int warp = threadIdx.x >> 5;
    int lane = threadIdx.x & 31;
    int t = blockIdx.x * 8 + warp;

    float acc[E_NUM];
#pragma unroll
    for (int e = 0; e < E_NUM; e++) acc[e] = 0.f;

    const float* xr = x + (size_t)t * C_DIM;
    for (int c = lane; c < C_DIM; c += 32) {
        float xv = xr[c];
        const float4* r = (const float4*)(rw + c * E_NUM);
        float4 r0 = r[0];
        float4 r1 = r[1];
        acc[0] += xv * r0.x; acc[1] += xv * r0.y;
        acc[2] += xv * r0.z; acc[3] += xv * r0.w;
        acc[4] += xv * r1.x; acc[5] += xv * r1.y;
        acc[6] += xv * r1.z; acc[7] += xv * r1.w;
    }
#pragma unroll
    for (int e = 0; e < E_NUM; e++) {
#pragma unroll
        for (int o = 16; o > 0; o >>= 1)
            acc[e] += __shfl_xor_sync(0xffffffffu, acc[e], o);
    }

    __shared__ float s_p[8][E_NUM];
    if (lane == 0) {
        float lg[E_NUM];
        float mx = -1e30f; int am = 0;
#pragma unroll
        for (int e = 0; e < E_NUM; e++) {
            lg[e] = acc[e] + rb[e];
            if (lg[e] > mx) { mx = lg[e]; am = e; }
        }
        float s = 0.f, p[E_NUM];
#pragma unroll
        for (int e = 0; e < E_NUM; e++) { p[e] = expf(lg[e] - mx); s += p[e]; }
        float inv = 1.f / s;
#pragma unroll
        for (int e = 0; e < E_NUM; e++) { p[e] *= inv; s_p[warp][e] = p[e]; }
        g_prob[t] = p[am];
        int pos = atomicAdd(&g_cnt[am], 1);
        g_idx[am * T_TOK + pos] = t;
    }
    __syncthreads();
    if (threadIdx.x < E_NUM) {
        int e = threadIdx.x;
        float s = 0.f;
#pragma unroll
        for (int w = 0; w < 8; w++) s += s_p[w][e];
        g_partial[blockIdx.x * E_NUM + e] = s;
    }
}

// ---------------------------------------------------------------------------
// Aux loss: parallel deterministic reduction.
__global__ void aux_kernel(float* __restrict__ out, int out_size) {
    __shared__ float s_e[E_NUM];
    int wid = threadIdx.x >> 5;
    int lane = threadIdx.x & 31;
    if (wid < E_NUM) {
        float s = 0.f;
#pragma unroll
        for (int j = 0; j < ROUTER_BLOCKS / 32; j++)
            s += g_partial[(j * 32 + lane) * E_NUM + wid];
#pragma unroll
        for (int o = 16; o > 0; o >>= 1)
            s += __shfl_xor_sync(0xffffffffu, s, o);
        if (lane == 0) {
            float imp = s * (1.f / (float)T_TOK);
            float load = (float)g_cnt[wid] * (1.f / (float)T_TOK);
            s_e[wid] = imp * load;
        }
    }
    __syncthreads();
    if (threadIdx.x == 0) {
        float a = 0.f;
        for (int e = 0; e < E_NUM; e++) a += s_e[e];
        out[out_size - 1] = (float)E_NUM * a;
    }
}

// ===========================================================================
// fp16 2-term GEMM on pre-converted planes.  A = Ah + Al; B = Bh.
// D = Ah*Bh + Al*Bh (2 MMAs per k16). Warp tile 32x32; BKK=32;
// double-buffered SMEM, one barrier per K-iteration. Plain LDG/STS only.
// ===========================================================================
#define LDSM4(r, a) \
    asm volatile("ldmatrix.sync.aligned.m8n8.x4.shared.b16 {%0,%1,%2,%3}, [%4];" \
        : "=r"((r)[0]), "=r"((r)[1]), "=r"((r)[2]), "=r"((r)[3]) : "r"(a))
#define LDSM4T(r, a) \
    asm volatile("ldmatrix.sync.aligned.m8n8.x4.trans.shared.b16 {%0,%1,%2,%3}, [%4];" \
        : "=r"((r)[0]), "=r"((r)[1]), "=r"((r)[2]), "=r"((r)[3]) : "r"(a))
#define MMA16816(d, a, b0, b1) \
    asm volatile("mma.sync.aligned.m16n8k16.row.col.f32.f16.f16.f32 " \
        "{%0,%1,%2,%3}, {%4,%5,%6,%7}, {%8,%9}, {%0,%1,%2,%3};" \
        : "+f"((d)[0]), "+f"((d)[1]), "+f"((d)[2]), "+f"((d)[3]) \
        : "r"((a)[0]), "r"((a)[1]), "r"((a)[2]), "r"((a)[3]), "r"(b0), "r"(b1))

__device__ __forceinline__ uint32_t sptr(const void* p) {
    return (uint32_t)__cvta_generic_to_shared(p);
}

#define BKK 32
#define ASTR 40     // padded A row (32 + 8 fp16)

// FFN1: D = silu(x @ w1 + b1) -> (g_hh, g_hl); FFN2: D = (h @ w2 + b2)*prob -> Df
template<int K_TOTAL, int A_STRIDE, int B_STRIDE, bool FFN1,
         int BMT, int BNT, int NT, int MINB>
__global__ void __launch_bounds__(NT, MINB)
ffn_mma_kernel(const __half* __restrict__ Ah, const __half* __restrict__ Al,
               const __half* __restrict__ Bh, const float* __restrict__ bias,
               __half* __restrict__ Dh, __half* __restrict__ Dl,
               float* __restrict__ Df) {
    constexpr int BSTR = BNT + 8;
    constexpr int APL  = BMT * ASTR * 2;          // bytes per A plane
    constexpr int BSZ  = BKK * BSTR * 2;          // bytes per B plane
    constexpr int O_AHs = 0;
    constexpr int O_ALs = APL;
    constexpr int O_BHs = 2 * APL;
    constexpr int BUF_BYTES = 2 * APL + BSZ;
    constexpr int NWN  = BNT / 32;                // warps along N
    constexpr int TPRA = NT / BMT;                // threads per A row
    constexpr int ACH  = 32 / (8 * TPRA);         // 16B chunks/plane/thread
    constexpr int TPRB = NT / BKK;                // threads per B row
    constexpr int BCH  = BNT / (8 * TPRB);        // 16B chunks/thread

    const int e = blockIdx.y;
    const int cnt = g_cnt[e];
    const int m0 = blockIdx.z * BMT;
    if (m0 >= cnt) return;
    const int n0 = blockIdx.x * BNT;

    extern __shared__ __align__(16) char dsm[];
    __shared__ int toks_s[BMT];

    const int tid = threadIdx.x;
    const int wid = tid >> 5;
    const int lane = tid & 31;
    const int warp_m = wid / NWN;
    const int warp_n = wid % NWN;

    if (tid < BMT) {
        int m = m0 + tid;
        toks_s[tid] = (m < cnt) ? g_idx[e * T_TOK + m] : -1;
    }
    __syncthreads();

    // loader mapping (invalid rows read token 0; outputs skipped in epilogue)
    const int a_row = tid / TPRA;
    const int a_c   = (tid % TPRA) * ACH;         // 8-half chunk idx within row
    const int tokA  = toks_s[a_row];
    const __half* aSrcH = Ah + (size_t)((tokA >= 0) ? tokA : 0) * A_STRIDE;
    const __half* aSrcL = Al + (size_t)((tokA >= 0) ? tokA : 0) * A_STRIDE;
    const int b_row = tid / TPRB;
    const int b_c   = (tid % TPRB) * BCH;
    const __half* bSrc = Bh + (size_t)e * K_TOTAL * B_STRIDE
                        + (size_t)b_row * B_STRIDE + n0 + b_c * 8;

    const uint32_t a_sts = (uint32_t)((a_row * ASTR + a_c * 8) * 2);
    const uint32_t b_sts = (uint32_t)((b_row * BSTR + b_c * 8) * 2);

    uint4 rah[ACH], ral[ACH], rbv[BCH];
#define LDG_TILE(k0) do { \
    _Pragma("unroll") \
    for (int j = 0; j < ACH; j++) { \
        rah[j] = *(const uint4*)(aSrcH + (k0) + (a_c + j) * 8); \
        ral[j] = *(const uint4*)(aSrcL + (k0) + (a_c + j) * 8); \
    } \
    _Pragma("unroll") \
    for (int j = 0; j < BCH; j++) \
        rbv[j] = *(const uint4*)(bSrc + (size_t)(k0) * B_STRIDE + j * 8); \
} while (0)
#define STS_TILE(base) do { \
    _Pragma("unroll") \
    for (int j = 0; j < ACH; j++) { \
        *(uint4*)((base) + O_AHs + a_sts + j * 16) = rah[j]; \
        *(uint4*)((base) + O_ALs + a_sts + j * 16) = ral[j]; \
    } \
    _Pragma("unroll") \
    for (int j = 0; j < BCH; j++) \
        *(uint4*)((base) + O_BHs + b_sts + j * 16) = rbv[j]; \
} while (0)

    // prologue: iter 0 -> buffer 0, prefetch iter 1
    LDG_TILE(0);
    STS_TILE(dsm);
    if (K_TOTAL > BKK) LDG_TILE(BKK);
    __syncthreads();

    float acc[2][4][4];
#pragma unroll
    for (int mi = 0; mi < 2; mi++)
#pragma unroll
        for (int nj = 0; nj < 4; nj++)
#pragma unroll
            for (int q = 0; q < 4; q++) acc[mi][nj][q] = 0.f;

    const uint32_t dynb = sptr(dsm);
    const int lm  = lane & 15;
    const int lg8 = (lane >> 4) * 8;
    const uint32_t aoff = (uint32_t)(((warp_m * 32 + lm) * ASTR + lg8) * 2);
    const uint32_t boff = (uint32_t)((lm * BSTR + warp_n * 32 + lg8) * 2);

    const int n_iters = K_TOTAL / BKK;
    for (int it = 0; it < n_iters; ++it) {
        const int cur = it & 1;

        // STS iter it+1 into the other buffer (its readers finished last iter)
        if (it + 1 < n_iters) {
            char* nb = dsm + (cur ^ 1) * BUF_BYTES;
            STS_TILE(nb);
        }
        // LDG iter it+2 into registers
        if (it + 2 < n_iters) LDG_TILE((it + 2) * BKK);

        // compute current buffer: 2 x k16 steps, 2-term fp16 split
        const uint32_t sb = dynb + cur * BUF_BYTES;
        const uint32_t aH = sb + O_AHs;
        const uint32_t aL = sb + O_ALs;
        const uint32_t bB = sb + O_BHs;
#pragma unroll
        for (int kk = 0; kk < 2; kk++) {
            uint32_t fah[2][4], fal[2][4], fbh[2][4];
#pragma unroll
            for (int ni = 0; ni < 2; ni++) {
                uint32_t ba = boff + (uint32_t)((kk * 16 * BSTR + ni * 16) * 2);
                LDSM4T(fbh[ni], bB + ba);
            }
#pragma unroll
            for (int mi = 0; mi < 2; mi++) {
                uint32_t aa = aoff + (uint32_t)((mi * 16 * ASTR + kk * 16) * 2);
                LDSM4(fah[mi], aH + aa);
                LDSM4(fal[mi], aL + aa);
            }
#pragma unroll
            for (int mi = 0; mi < 2; mi++) {
#pragma unroll
                for (int nj = 0; nj < 4; nj++) {
                    uint32_t b0 = fbh[nj >> 1][(nj & 1) * 2];
                    uint32_t b1 = fbh[nj >> 1][(nj & 1) * 2 + 1];
                    MMA16816(acc[mi][nj], fah[mi], b0, b1);
                    MMA16816(acc[mi][nj], fal[mi], b0, b1);
                }
            }
        }
        __syncthreads();
    }
#undef LDG_TILE
#undef STS_TILE

    // epilogue: straight from registers
    const int r4 = lane >> 2;
    const int c2 = (lane & 3) * 2;
    const float* bias_p = bias + (size_t)e * B_STRIDE + n0 + warp_n * 32;
#pragma unroll
    for (int mi = 0; mi < 2; mi++) {
#pragma unroll
        for (int half_ = 0; half_ < 2; half_++) {
            int rl = warp_m * 32 + mi * 16 + half_ * 8 + r4;
            int tok = toks_s[rl];
            if (tok < 0) continue;
#pragma unroll
            for (int nj = 0; nj < 4; nj++) {
                int c = nj * 8 + c2;
                float v0 = acc[mi][nj][half_ * 2 + 0] + bias_p[c];
                float v1 = acc[mi][nj][half_ * 2 + 1] + bias_p[c + 1];
                if (FFN1) {
                    v0 = v0 / (1.f + expf(-v0));
                    v1 = v1 / (1.f + expf(-v1));
                    __half h0 = __float2half_rn(v0);
                    __half h1 = __float2half_rn(v1);
                    __half l0 = __float2half_rn(v0 - __half2float(h0));
                    __half l1 = __float2half_rn(v1 - __half2float(h1));
                    size_t o = (size_t)tok * B_STRIDE + n0 + warp_n * 32 + c;
                    *(__half2*)(Dh + o) = __halves2half2(h0, h1);
                    *(__half2*)(Dl + o) = __halves2half2(l0, l1);
                } else {
                    float p = g_prob[tok];
                    float2 o2;
                    o2.x = v0 * p;
                    o2.y = v1 * p;
                    *(float2*)(Df + (size_t)tok * B_STRIDE + n0 + warp_n * 32 + c) = o2;
                }
            }
        }
    }
}

// ---------------------------------------------------------------------------
// FFN1: BM=128, BN=128, 512 threads. FFN2: BM=64, BN=64, 128 threads.
#define F1_SMEM (2 * (2 * (128 * ASTR * 2) + (BKK * (128 + 8) * 2)))   // 58368
#define F2_SMEM (2 * (2 * (64 * ASTR * 2) + (BKK * (64 + 8) * 2)))     // 29696

extern "C" void kernel_launch(void* const* d_in, const int* in_sizes, int n_in,
                              void* d_out, int out_size) {
    const float* x  = (const float*)d_in[0];
    const float* rw = (const float*)d_in[1];
    const float* rb = (const float*)d_in[2];
    const float* w1 = (const float*)d_in[3];
    const float* b1 = (const float*)d_in[4];
    const float* w2 = (const float*)d_in[5];
    const float* b2 = (const float*)d_in[6];
    float* out = (float*)d_out;

    cudaFuncSetAttribute(
        ffn_mma_kernel<C_DIM, C_DIM, F_DIM, true, 128, 128, 512, 1>,
        cudaFuncAttributeMaxDynamicSharedMemorySize, F1_SMEM);
    cudaFuncSetAttribute(
        ffn_mma_kernel<F_DIM, F_DIM, C_DIM, false, 64, 64, 128, 2>,
        cudaFuncAttributeMaxDynamicSharedMemorySize, F2_SMEM);

    __half *xh, *xl, *w1h, *w2h, *hh, *hl;
    cudaGetSymbolAddress((void**)&xh,  g_xh);
    cudaGetSymbolAddress((void**)&xl,  g_xl);
    cudaGetSymbolAddress((void**)&w1h, g_w1h);
    cudaGetSymbolAddress((void**)&w2h, g_w2h);
    cudaGetSymbolAddress((void**)&hh,  g_hh);
    cudaGetSymbolAddress((void**)&hl,  g_hl);

    init_kernel<<<1, 32>>>();
    // operand prep (streaming, ILP-4)
    const int n4w = E_NUM * C_DIM * F_DIM / 4;   // 8388608 = 4 * (2048*256) * 4
    cvt_w_kernel<<<2048, 256>>>((const float4*)w1, (uint2*)w1h, n4w);
    cvt_w_kernel<<<2048, 256>>>((const float4*)w2, (uint2*)w2h, n4w);
    cvt_split_kernel<<<512, 256>>>((const float4*)x, (uint2*)xh, (uint2*)xl,
                                   T_TOK * C_DIM / 4);
    router_kernel<<<ROUTER_BLOCKS, 256>>>(x, rw, rb);
    aux_kernel<<<1, 256>>>(out, out_size);

    // FFN1: [cnt_e,1024] @ [1024,4096] -> silu -> (g_hh, g_hl)
    ffn_mma_kernel<C_DIM, C_DIM, F_DIM, true, 128, 128, 512, 1>
        <<<dim3(F_DIM / 128, E_NUM, T_TOK / 128), 512, F1_SMEM>>>(
            xh, xl, w1h, b1, hh, hl, nullptr);
    // FFN2: [cnt_e,4096] @ [4096,1024] -> *prob -> out
    ffn_mma_kernel<F_DIM, F_DIM, C_DIM, false, 64, 64, 128, 2>
        <<<dim3(C_DIM / 64, E_NUM, T_TOK / 64), 128, F2_SMEM>>>(
            hh, hl, w2h, b2, nullptr, nullptr, out);
}

// round 14
// speedup vs baseline: 1.0899x; 1.0757x over previous
#include <cuda_runtime.h>
#include <cuda_fp16.h>
#include <math.h>
#include <stdint.h>

// Problem constants
#define T_TOK 2048
#define C_DIM 1024
#define F_DIM 4096
#define E_NUM 8
#define ROUTER_BLOCKS 256   // 8 tokens (warps) per block

// Scratch (allocation-free rule: __device__ globals)
__device__ int   g_cnt[E_NUM];
__device__ int   g_idx[E_NUM * T_TOK];
__device__ float g_prob[T_TOK];
__device__ float g_partial[ROUTER_BLOCKS * E_NUM];
// fp16 operand planes
__device__ __align__(256) __half g_xh[(size_t)T_TOK * C_DIM];
__device__ __align__(256) __half g_xl[(size_t)T_TOK * C_DIM];
__device__ __align__(256) __half g_w1h[(size_t)E_NUM * C_DIM * F_DIM];
__device__ __align__(256) __half g_w2h[(size_t)E_NUM * F_DIM * C_DIM];
__device__ __align__(256) __half g_hh[(size_t)T_TOK * F_DIM];
__device__ __align__(256) __half g_hl[(size_t)T_TOK * F_DIM];

// ---------------------------------------------------------------------------
__global__ void init_kernel() {
    int i = threadIdx.x;
    if (i < E_NUM) g_cnt[i] = 0;
}

// Streaming converters (ILP-4, streaming loads/stores) ----------------------
// Converts BOTH weight tensors in one launch (halves launch/tail overhead).
__global__ void cvt_w2_kernel(const float4* __restrict__ wa,
                              const float4* __restrict__ wb,
                              uint2* __restrict__ da,
                              uint2* __restrict__ db, int n4) {
    const int stride = gridDim.x * blockDim.x;
    const int i0 = blockIdx.x * blockDim.x + threadIdx.x;
    const int total = 2 * n4;
    for (int base = i0; base < total; base += 4 * stride) {
        float4 f[4];
#pragma unroll
        for (int j = 0; j < 4; j++) {
            int i = base + j * stride;
            if (i < total)
                f[j] = (i < n4) ? __ldcs(&wa[i]) : __ldcs(&wb[i - n4]);
        }
#pragma unroll
        for (int j = 0; j < 4; j++) {
            int i = base + j * stride;
            if (i < total) {
                __half2 a = __floats2half2_rn(f[j].x, f[j].y);
                __half2 b = __floats2half2_rn(f[j].z, f[j].w);
                uint2 v = make_uint2(*(uint32_t*)&a, *(uint32_t*)&b);
                if (i < n4) __stcs(&da[i], v);
                else        __stcs(&db[i - n4], v);
            }
        }
    }
}
__global__ void cvt_split_kernel(const float4* __restrict__ x,
                                 uint2* __restrict__ xh, uint2* __restrict__ xl,
                                 int n4) {
    const int stride = gridDim.x * blockDim.x;
    const int i0 = blockIdx.x * blockDim.x + threadIdx.x;
    for (int base = i0; base < n4; base += 4 * stride) {
        float4 f[4];
#pragma unroll
        for (int j = 0; j < 4; j++) {
            int i = base + j * stride;
            if (i < n4) f[j] = __ldcs(&x[i]);
        }
#pragma unroll
        for (int j = 0; j < 4; j++) {
            int i = base + j * stride;
            if (i < n4) {
                __half2 h01 = __floats2half2_rn(f[j].x, f[j].y);
                __half2 h23 = __floats2half2_rn(f[j].z, f[j].w);
                float rx = f[j].x - __low2float(h01);
                float ry = f[j].y - __high2float(h01);
                float rz = f[j].z - __low2float(h23);
                float rw = f[j].w - __high2float(h23);
                __half2 l01 = __floats2half2_rn(rx, ry);
                __half2 l23 = __floats2half2_rn(rz, rw);
                __stcs(&xh[i], make_uint2(*(uint32_t*)&h01, *(uint32_t*)&h23));
                __stcs(&xl[i], make_uint2(*(uint32_t*)&l01, *(uint32_t*)&l23));
            }
        }
    }
}

// ---------------------------------------------------------------------------
// Router: one warp per token. Deterministic importance partials per block.
__global__ void router_kernel(const float* __restrict__ x,
                              const float* __restrict__ rw,
                              const float* __restrict__ rb) {
    int warp = threadIdx.x >> 5;
    int lane = threadIdx.x & 31;
    int t = blockIdx.x * 8 + warp;

    float acc[E_NUM];
#pragma unroll
    for (int e = 0; e < E_NUM; e++) acc[e] = 0.f;

    const float* xr = x + (size_t)t * C_DIM;
    for (int c = lane; c < C_DIM; c += 32) {
        float xv = xr[c];
        const float4* r = (const float4*)(rw + c * E_NUM);
        float4 r0 = r[0];
        float4 r1 = r[1];
        acc[0] += xv * r0.x; acc[1] += xv * r0.y;
        acc[2] += xv * r0.z; acc[3] += xv * r0.w;
        acc[4] += xv * r1.x; acc[5] += xv * r1.y;
        acc[6] += xv * r1.z; acc[7] += xv * r1.w;
    }
#pragma unroll
    for (int e = 0; e < E_NUM; e++) {
#pragma unroll
        for (int o = 16; o > 0; o >>= 1)
            acc[e] += __shfl_xor_sync(0xffffffffu, acc[e], o);
    }

    __shared__ float s_p[8][E_NUM];
    if (lane == 0) {
        float lg[E_NUM];
        float mx = -1e30f; int am = 0;
#pragma unroll
        for (int e = 0; e < E_NUM; e++) {
            lg[e] = acc[e] + rb[e];
            if (lg[e] > mx) { mx = lg[e]; am = e; }
        }
        float s = 0.f, p[E_NUM];
#pragma unroll
        for (int e = 0; e < E_NUM; e++) { p[e] = expf(lg[e] - mx); s += p[e]; }
        float inv = 1.f / s;
#pragma unroll
        for (int e = 0; e < E_NUM; e++) { p[e] *= inv; s_p[warp][e] = p[e]; }
        g_prob[t] = p[am];
        int pos = atomicAdd(&g_cnt[am], 1);
        g_idx[am * T_TOK + pos] = t;
    }
    __syncthreads();
    if (threadIdx.x < E_NUM) {
        int e = threadIdx.x;
        float s = 0.f;
#pragma unroll
        for (int w = 0; w < 8; w++) s += s_p[w][e];
        g_partial[blockIdx.x * E_NUM + e] = s;
    }
}

// ---------------------------------------------------------------------------
// Aux loss: parallel deterministic reduction.
__global__ void aux_kernel(float* __restrict__ out, int out_size) {
    __shared__ float s_e[E_NUM];
    int wid = threadIdx.x >> 5;
    int lane = threadIdx.x & 31;
    if (wid < E_NUM) {
        float s = 0.f;
#pragma unroll
        for (int j = 0; j < ROUTER_BLOCKS / 32; j++)
            s += g_partial[(j * 32 + lane) * E_NUM + wid];
#pragma unroll
        for (int o = 16; o > 0; o >>= 1)
            s += __shfl_xor_sync(0xffffffffu, s, o);
        if (lane == 0) {
            float imp = s * (1.f / (float)T_TOK);
            float load = (float)g_cnt[wid] * (1.f / (float)T_TOK);
            s_e[wid] = imp * load;
        }
    }
    __syncthreads();
    if (threadIdx.x == 0) {
        float a = 0.f;
        for (int e = 0; e < E_NUM; e++) a += s_e[e];
        out[out_size - 1] = (float)E_NUM * a;
    }
}

// ===========================================================================
// fp16 2-term GEMM on pre-converted planes.  A = Ah + Al; B = Bh.
// D = Ah*Bh + Al*Bh (2 MMAs per k16). Warp tile 32x32; BKK=32;
// double-buffered SMEM, one barrier per K-iteration. Plain LDG/STS only.
// ===========================================================================
#define LDSM4(r, a) \
    asm volatile("ldmatrix.sync.aligned.m8n8.x4.shared.b16 {%0,%1,%2,%3}, [%4];" \
        : "=r"((r)[0]), "=r"((r)[1]), "=r"((r)[2]), "=r"((r)[3]) : "r"(a))
#define LDSM4T(r, a) \
    asm volatile("ldmatrix.sync.aligned.m8n8.x4.trans.shared.b16 {%0,%1,%2,%3}, [%4];" \
        : "=r"((r)[0]), "=r"((r)[1]), "=r"((r)[2]), "=r"((r)[3]) : "r"(a))
#define MMA16816(d, a, b0, b1) \
    asm volatile("mma.sync.aligned.m16n8k16.row.col.f32.f16.f16.f32 " \
        "{%0,%1,%2,%3}, {%4,%5,%6,%7}, {%8,%9}, {%0,%1,%2,%3};" \
        : "+f"((d)[0]), "+f"((d)[1]), "+f"((d)[2]), "+f"((d)[3]) \
        : "r"((a)[0]), "r"((a)[1]), "r"((a)[2]), "r"((a)[3]), "r"(b0), "r"(b1))

__device__ __forceinline__ uint32_t sptr(const void* p) {
    return (uint32_t)__cvta_generic_to_shared(p);
}

#define BKK 32
#define ASTR 40     // padded A row (32 + 8 fp16)

// FFN1: D = silu(x @ w1 + b1) -> (g_hh, g_hl); FFN2: D = (h @ w2 + b2)*prob -> Df
template<int K_TOTAL, int A_STRIDE, int B_STRIDE, bool FFN1,
         int BMT, int BNT, int NT, int MINB>
__global__ void __launch_bounds__(NT, MINB)
ffn_mma_kernel(const __half* __restrict__ Ah, const __half* __restrict__ Al,
               const __half* __restrict__ Bh, const float* __restrict__ bias,
               __half* __restrict__ Dh, __half* __restrict__ Dl,
               float* __restrict__ Df) {
    constexpr int BSTR = BNT + 8;
    constexpr int APL  = BMT * ASTR * 2;          // bytes per A plane
    constexpr int BSZ  = BKK * BSTR * 2;          // bytes per B plane
    constexpr int O_AHs = 0;
    constexpr int O_ALs = APL;
    constexpr int O_BHs = 2 * APL;
    constexpr int BUF_BYTES = 2 * APL + BSZ;
    constexpr int NWN  = BNT / 32;                // warps along N
    constexpr int TPRA = NT / BMT;                // threads per A row
    constexpr int ACH  = 32 / (8 * TPRA);         // 16B chunks/plane/thread
    constexpr int TPRB = NT / BKK;                // threads per B row
    constexpr int BCH  = BNT / (8 * TPRB);        // 16B chunks/thread

    const int e = blockIdx.y;
    const int cnt = g_cnt[e];
    const int m0 = blockIdx.z * BMT;
    if (m0 >= cnt) return;
    const int n0 = blockIdx.x * BNT;

    extern __shared__ __align__(16) char dsm[];
    __shared__ int toks_s[BMT];

    const int tid = threadIdx.x;
    const int wid = tid >> 5;
    const int lane = tid & 31;
    const int warp_m = wid / NWN;
    const int warp_n = wid % NWN;

    if (tid < BMT) {
        int m = m0 + tid;
        toks_s[tid] = (m < cnt) ? g_idx[e * T_TOK + m] : -1;
    }
    __syncthreads();

    // loader mapping (invalid rows read token 0; outputs skipped in epilogue)
    const int a_row = tid / TPRA;
    const int a_c   = (tid % TPRA) * ACH;         // 8-half chunk idx within row
    const int tokA  = toks_s[a_row];
    const __half* aSrcH = Ah + (size_t)((tokA >= 0) ? tokA : 0) * A_STRIDE;
    const __half* aSrcL = Al + (size_t)((tokA >= 0) ? tokA : 0) * A_STRIDE;
    const int b_row = tid / TPRB;
    const int b_c   = (tid % TPRB) * BCH;
    const __half* bSrc = Bh + (size_t)e * K_TOTAL * B_STRIDE
                        + (size_t)b_row * B_STRIDE + n0 + b_c * 8;

    const uint32_t a_sts = (uint32_t)((a_row * ASTR + a_c * 8) * 2);
    const uint32_t b_sts = (uint32_t)((b_row * BSTR + b_c * 8) * 2);

    uint4 rah[ACH], ral[ACH], rbv[BCH];
#define LDG_TILE(k0) do { \
    _Pragma("unroll") \
    for (int j = 0; j < ACH; j++) { \
        rah[j] = *(const uint4*)(aSrcH + (k0) + (a_c + j) * 8); \
        ral[j] = *(const uint4*)(aSrcL + (k0) + (a_c + j) * 8); \
    } \
    _Pragma("unroll") \
    for (int j = 0; j < BCH; j++) \
        rbv[j] = *(const uint4*)(bSrc + (size_t)(k0) * B_STRIDE + j * 8); \
} while (0)
#define STS_TILE(base) do { \
    _Pragma("unroll") \
    for (int j = 0; j < ACH; j++) { \
        *(uint4*)((base) + O_AHs + a_sts + j * 16) = rah[j]; \
        *(uint4*)((base) + O_ALs + a_sts + j * 16) = ral[j]; \
    } \
    _Pragma("unroll") \
    for (int j = 0; j < BCH; j++) \
        *(uint4*)((base) + O_BHs + b_sts + j * 16) = rbv[j]; \
} while (0)

    // prologue: iter 0 -> buffer 0, prefetch iter 1
    LDG_TILE(0);
    STS_TILE(dsm);
    if (K_TOTAL > BKK) LDG_TILE(BKK);
    __syncthreads();

    float acc[2][4][4];
#pragma unroll
    for (int mi = 0; mi < 2; mi++)
#pragma unroll
        for (int nj = 0; nj < 4; nj++)
#pragma unroll
            for (int q = 0; q < 4; q++) acc[mi][nj][q] = 0.f;

    const uint32_t dynb = sptr(dsm);
    const int lm  = lane & 15;
    const int lg8 = (lane >> 4) * 8;
    const uint32_t aoff = (uint32_t)(((warp_m * 32 + lm) * ASTR + lg8) * 2);
    const uint32_t boff = (uint32_t)((lm * BSTR + warp_n * 32 + lg8) * 2);

    const int n_iters = K_TOTAL / BKK;
    for (int it = 0; it < n_iters; ++it) {
        const int cur = it & 1;

        // STS iter it+1 into the other buffer (its readers finished last iter)
        if (it + 1 < n_iters) {
            char* nb = dsm + (cur ^ 1) * BUF_BYTES;
            STS_TILE(nb);
        }
        // LDG iter it+2 into registers
        if (it + 2 < n_iters) LDG_TILE((it + 2) * BKK);

        // compute current buffer: 2 x k16 steps, 2-term fp16 split
        const uint32_t sb = dynb + cur * BUF_BYTES;
        const uint32_t aH = sb + O_AHs;
        const uint32_t aL = sb + O_ALs;
        const uint32_t bB = sb + O_BHs;
#pragma unroll
        for (int kk = 0; kk < 2; kk++) {
            uint32_t fah[2][4], fal[2][4], fbh[2][4];
#pragma unroll
            for (int ni = 0; ni < 2; ni++) {
                uint32_t ba = boff + (uint32_t)((kk * 16 * BSTR + ni * 16) * 2);
                LDSM4T(fbh[ni], bB + ba);
            }
#pragma unroll
            for (int mi = 0; mi < 2; mi++) {
                uint32_t aa = aoff + (uint32_t)((mi * 16 * ASTR + kk * 16) * 2);
                LDSM4(fah[mi], aH + aa);
                LDSM4(fal[mi], aL + aa);
            }
#pragma unroll
            for (int mi = 0; mi < 2; mi++) {
#pragma unroll
                for (int nj = 0; nj < 4; nj++) {
                    uint32_t b0 = fbh[nj >> 1][(nj & 1) * 2];
                    uint32_t b1 = fbh[nj >> 1][(nj & 1) * 2 + 1];
                    MMA16816(acc[mi][nj], fah[mi], b0, b1);
                    MMA16816(acc[mi][nj], fal[mi], b0, b1);
                }
            }
        }
        __syncthreads();
    }
#undef LDG_TILE
#undef STS_TILE

    // epilogue: straight from registers
    const int r4 = lane >> 2;
    const int c2 = (lane & 3) * 2;
    const float* bias_p = bias + (size_t)e * B_STRIDE + n0 + warp_n * 32;
#pragma unroll
    for (int mi = 0; mi < 2; mi++) {
#pragma unroll
        for (int half_ = 0; half_ < 2; half_++) {
            int rl = warp_m * 32 + mi * 16 + half_ * 8 + r4;
            int tok = toks_s[rl];
            if (tok < 0) continue;
#pragma unroll
            for (int nj = 0; nj < 4; nj++) {
                int c = nj * 8 + c2;
                float v0 = acc[mi][nj][half_ * 2 + 0] + bias_p[c];
                float v1 = acc[mi][nj][half_ * 2 + 1] + bias_p[c + 1];
                if (FFN1) {
                    v0 = v0 / (1.f + expf(-v0));
                    v1 = v1 / (1.f + expf(-v1));
                    __half h0 = __float2half_rn(v0);
                    __half h1 = __float2half_rn(v1);
                    __half l0 = __float2half_rn(v0 - __half2float(h0));
                    __half l1 = __float2half_rn(v1 - __half2float(h1));
                    size_t o = (size_t)tok * B_STRIDE + n0 + warp_n * 32 + c;
                    *(__half2*)(Dh + o) = __halves2half2(h0, h1);
                    *(__half2*)(Dl + o) = __halves2half2(l0, l1);
                } else {
                    float p = g_prob[tok];
                    float2 o2;
                    o2.x = v0 * p;
                    o2.y = v1 * p;
                    *(float2*)(Df + (size_t)tok * B_STRIDE + n0 + warp_n * 32 + c) = o2;
                }
            }
        }
    }
}

// ---------------------------------------------------------------------------
// FFN1: BM=64, BN=128, 256 threads, MINB=2 (multi-CTA overlap).
// FFN2: BM=64, BN=64, 128 threads, MINB=2.
#define F1_SMEM (2 * (2 * (64 * ASTR * 2) + (BKK * (128 + 8) * 2)))    // 37888
#define F2_SMEM (2 * (2 * (64 * ASTR * 2) + (BKK * (64 + 8) * 2)))     // 29696

extern "C" void kernel_launch(void* const* d_in, const int* in_sizes, int n_in,
                              void* d_out, int out_size) {
    const float* x  = (const float*)d_in[0];
    const float* rw = (const float*)d_in[1];
    const float* rb = (const float*)d_in[2];
    const float* w1 = (const float*)d_in[3];
    const float* b1 = (const float*)d_in[4];
    const float* w2 = (const float*)d_in[5];
    const float* b2 = (const float*)d_in[6];
    float* out = (float*)d_out;

    cudaFuncSetAttribute(
        ffn_mma_kernel<C_DIM, C_DIM, F_DIM, true, 64, 128, 256, 2>,
        cudaFuncAttributeMaxDynamicSharedMemorySize, F1_SMEM);
    cudaFuncSetAttribute(
        ffn_mma_kernel<F_DIM, F_DIM, C_DIM, false, 64, 64, 128, 2>,
        cudaFuncAttributeMaxDynamicSharedMemorySize, F2_SMEM);

    __half *xh, *xl, *w1h, *w2h, *hh, *hl;
    cudaGetSymbolAddress((void**)&xh,  g_xh);
    cudaGetSymbolAddress((void**)&xl,  g_xl);
    cudaGetSymbolAddress((void**)&w1h, g_w1h);
    cudaGetSymbolAddress((void**)&w2h, g_w2h);
    cudaGetSymbolAddress((void**)&hh,  g_hh);
    cudaGetSymbolAddress((void**)&hl,  g_hl);

    init_kernel<<<1, 32>>>();
    // operand prep (streaming, ILP-4; both weight tensors in one launch)
    const int n4w = E_NUM * C_DIM * F_DIM / 4;
    cvt_w2_kernel<<<4096, 256>>>((const float4*)w1, (const float4*)w2,
                                 (uint2*)w1h, (uint2*)w2h, n4w);
    cvt_split_kernel<<<512, 256>>>((const float4*)x, (uint2*)xh, (uint2*)xl,
                                   T_TOK * C_DIM / 4);
    router_kernel<<<ROUTER_BLOCKS, 256>>>(x, rw, rb);
    aux_kernel<<<1, 256>>>(out, out_size);

    // FFN1: [cnt_e,1024] @ [1024,4096] -> silu -> (g_hh, g_hl)
    ffn_mma_kernel<C_DIM, C_DIM, F_DIM, true, 64, 128, 256, 2>
        <<<dim3(F_DIM / 128, E_NUM, T_TOK / 64), 256, F1_SMEM>>>(
            xh, xl, w1h, b1, hh, hl, nullptr);
    // FFN2: [cnt_e,4096] @ [4096,1024] -> *prob -> out
    ffn_mma_kernel<F_DIM, F_DIM, C_DIM, false, 64, 64, 128, 2>
        <<<dim3(C_DIM / 64, E_NUM, T_TOK / 64), 128, F2_SMEM>>>(
            hh, hl, w2h, b2, nullptr, nullptr, out);
}

// round 15
// speedup vs baseline: 1.0945x; 1.0042x over previous
#include <cuda_runtime.h>
#include <cuda_fp16.h>
#include <math.h>
#include <stdint.h>

// Problem constants
#define T_TOK 2048
#define C_DIM 1024
#define F_DIM 4096
#define E_NUM 8
#define ROUTER_BLOCKS 256   // 8 tokens (warps) per block

// Scratch (allocation-free rule: __device__ globals)
__device__ int   g_cnt[E_NUM];
__device__ int   g_idx[E_NUM * T_TOK];
__device__ float g_prob[T_TOK];
__device__ float g_partial[ROUTER_BLOCKS * E_NUM];
// fp16 operand planes
__device__ __align__(256) __half g_xh[(size_t)T_TOK * C_DIM];
__device__ __align__(256) __half g_xl[(size_t)T_TOK * C_DIM];
__device__ __align__(256) __half g_w1h[(size_t)E_NUM * C_DIM * F_DIM];
__device__ __align__(256) __half g_w2h[(size_t)E_NUM * F_DIM * C_DIM];
__device__ __align__(256) __half g_hh[(size_t)T_TOK * F_DIM];
__device__ __align__(256) __half g_hl[(size_t)T_TOK * F_DIM];

// ---------------------------------------------------------------------------
__global__ void init_kernel() {
    int i = threadIdx.x;
    if (i < E_NUM) g_cnt[i] = 0;
}

// Streaming converters: 2x float4 loads -> 1x uint4 (16B) store, ILP-2 ------
__device__ __forceinline__ uint4 pack8_fp16(float4 f0, float4 f1) {
    __half2 a = __floats2half2_rn(f0.x, f0.y);
    __half2 b = __floats2half2_rn(f0.z, f0.w);
    __half2 c = __floats2half2_rn(f1.x, f1.y);
    __half2 d = __floats2half2_rn(f1.z, f1.w);
    return make_uint4(*(uint32_t*)&a, *(uint32_t*)&b,
                      *(uint32_t*)&c, *(uint32_t*)&d);
}

// Converts BOTH weight tensors in one launch. n8 = uint4 outputs per tensor.
__global__ void cvt_w2_kernel(const float4* __restrict__ wa,
                              const float4* __restrict__ wb,
                              uint4* __restrict__ da,
                              uint4* __restrict__ db, int n8) {
    const int stride = gridDim.x * blockDim.x;
    const int i0 = blockIdx.x * blockDim.x + threadIdx.x;
    const int total = 2 * n8;
    for (int base = i0; base < total; base += 2 * stride) {
        float4 f0[2], f1[2];
#pragma unroll
        for (int j = 0; j < 2; j++) {
            int i = base + j * stride;
            if (i < total) {
                const float4* src = (i < n8) ? (wa + 2 * (size_t)i)
                                             : (wb + 2 * (size_t)(i - n8));
                f0[j] = __ldcs(src);
                f1[j] = __ldcs(src + 1);
            }
        }
#pragma unroll
        for (int j = 0; j < 2; j++) {
            int i = base + j * stride;
            if (i < total) {
                uint4 v = pack8_fp16(f0[j], f1[j]);
                if (i < n8) __stcs(&da[i], v);
                else        __stcs(&db[i - n8], v);
            }
        }
    }
}
// x -> hi/lo planes; n8 = uint4 outputs per plane.
__global__ void cvt_split_kernel(const float4* __restrict__ x,
                                 uint4* __restrict__ xh, uint4* __restrict__ xl,
                                 int n8) {
    const int stride = gridDim.x * blockDim.x;
    const int i0 = blockIdx.x * blockDim.x + threadIdx.x;
    for (int i = i0; i < n8; i += stride) {
        float4 f0 = __ldcs(x + 2 * (size_t)i);
        float4 f1 = __ldcs(x + 2 * (size_t)i + 1);
        uint4 hv = pack8_fp16(f0, f1);
        __half2 h01 = *(__half2*)&hv.x;
        __half2 h23 = *(__half2*)&hv.y;
        __half2 h45 = *(__half2*)&hv.z;
        __half2 h67 = *(__half2*)&hv.w;
        float4 r0, r1;
        r0.x = f0.x - __low2float(h01);  r0.y = f0.y - __high2float(h01);
        r0.z = f0.z - __low2float(h23);  r0.w = f0.w - __high2float(h23);
        r1.x = f1.x - __low2float(h45);  r1.y = f1.y - __high2float(h45);
        r1.z = f1.z - __low2float(h67);  r1.w = f1.w - __high2float(h67);
        uint4 lv = pack8_fp16(r0, r1);
        __stcs(&xh[i], hv);
        __stcs(&xl[i], lv);
    }
}

// ---------------------------------------------------------------------------
// Router: one warp per token. Deterministic importance partials per block.
__global__ void router_kernel(const float* __restrict__ x,
                              const float* __restrict__ rw,
                              const float* __restrict__ rb) {
    int warp = threadIdx.x >> 5;
    int lane = threadIdx.x & 31;
    int t = blockIdx.x * 8 + warp;

    float acc[E_NUM];
#pragma unroll
    for (int e = 0; e < E_NUM; e++) acc[e] = 0.f;

    const float* xr = x + (size_t)t * C_DIM;
    for (int c = lane; c < C_DIM; c += 32) {
        float xv = xr[c];
        const float4* r = (const float4*)(rw + c * E_NUM);
        float4 r0 = r[0];
        float4 r1 = r[1];
        acc[0] += xv * r0.x; acc[1] += xv * r0.y;
        acc[2] += xv * r0.z; acc[3] += xv * r0.w;
        acc[4] += xv * r1.x; acc[5] += xv * r1.y;
        acc[6] += xv * r1.z; acc[7] += xv * r1.w;
    }
#pragma unroll
    for (int e = 0; e < E_NUM; e++) {
#pragma unroll
        for (int o = 16; o > 0; o >>= 1)
            acc[e] += __shfl_xor_sync(0xffffffffu, acc[e], o);
    }

    __shared__ float s_p[8][E_NUM];
    if (lane == 0) {
        float lg[E_NUM];
        float mx = -1e30f; int am = 0;
#pragma unroll
        for (int e = 0; e < E_NUM; e++) {
            lg[e] = acc[e] + rb[e];
            if (lg[e] > mx) { mx = lg[e]; am = e; }
        }
        float s = 0.f, p[E_NUM];
#pragma unroll
        for (int e = 0; e < E_NUM; e++) { p[e] = expf(lg[e] - mx); s += p[e]; }
        float inv = 1.f / s;
#pragma unroll
        for (int e = 0; e < E_NUM; e++) { p[e] *= inv; s_p[warp][e] = p[e]; }
        g_prob[t] = p[am];
        int pos = atomicAdd(&g_cnt[am], 1);
        g_idx[am * T_TOK + pos] = t;
    }
    __syncthreads();
    if (threadIdx.x < E_NUM) {
        int e = threadIdx.x;
        float s = 0.f;
#pragma unroll
        for (int w = 0; w < 8; w++) s += s_p[w][e];
        g_partial[blockIdx.x * E_NUM + e] = s;
    }
}

// ---------------------------------------------------------------------------
// Aux loss: parallel deterministic reduction.
__global__ void aux_kernel(float* __restrict__ out, int out_size) {
    __shared__ float s_e[E_NUM];
    int wid = threadIdx.x >> 5;
    int lane = threadIdx.x & 31;
    if (wid < E_NUM) {
        float s = 0.f;
#pragma unroll
        for (int j = 0; j < ROUTER_BLOCKS / 32; j++)
            s += g_partial[(j * 32 + lane) * E_NUM + wid];
#pragma unroll
        for (int o = 16; o > 0; o >>= 1)
            s += __shfl_xor_sync(0xffffffffu, s, o);
        if (lane == 0) {
            float imp = s * (1.f / (float)T_TOK);
            float load = (float)g_cnt[wid] * (1.f / (float)T_TOK);
            s_e[wid] = imp * load;
        }
    }
    __syncthreads();
    if (threadIdx.x == 0) {
        float a = 0.f;
        for (int e = 0; e < E_NUM; e++) a += s_e[e];
        out[out_size - 1] = (float)E_NUM * a;
    }
}

// ===========================================================================
// fp16 2-term GEMM on pre-converted planes.  A = Ah + Al; B = Bh.
// D = Ah*Bh + Al*Bh (2 MMAs per k16). Warp tile 32x32; BKK=32;
// double-buffered SMEM, one barrier per K-iteration. Plain LDG/STS only.
// ===========================================================================
#define LDSM4(r, a) \
    asm volatile("ldmatrix.sync.aligned.m8n8.x4.shared.b16 {%0,%1,%2,%3}, [%4];" \
        : "=r"((r)[0]), "=r"((r)[1]), "=r"((r)[2]), "=r"((r)[3]) : "r"(a))
#define LDSM4T(r, a) \
    asm volatile("ldmatrix.sync.aligned.m8n8.x4.trans.shared.b16 {%0,%1,%2,%3}, [%4];" \
        : "=r"((r)[0]), "=r"((r)[1]), "=r"((r)[2]), "=r"((r)[3]) : "r"(a))
#define MMA16816(d, a, b0, b1) \
    asm volatile("mma.sync.aligned.m16n8k16.row.col.f32.f16.f16.f32 " \
        "{%0,%1,%2,%3}, {%4,%5,%6,%7}, {%8,%9}, {%0,%1,%2,%3};" \
        : "+f"((d)[0]), "+f"((d)[1]), "+f"((d)[2]), "+f"((d)[3]) \
        : "r"((a)[0]), "r"((a)[1]), "r"((a)[2]), "r"((a)[3]), "r"(b0), "r"(b1))

__device__ __forceinline__ uint32_t sptr(const void* p) {
    return (uint32_t)__cvta_generic_to_shared(p);
}

#define BKK 32
#define ASTR 40     // padded A row (32 + 8 fp16)

// FFN1: D = silu(x @ w1 + b1) -> (g_hh, g_hl); FFN2: D = (h @ w2 + b2)*prob -> Df
template<int K_TOTAL, int A_STRIDE, int B_STRIDE, bool FFN1,
         int BMT, int BNT, int NT, int MINB>
__global__ void __launch_bounds__(NT, MINB)
ffn_mma_kernel(const __half* __restrict__ Ah, const __half* __restrict__ Al,
               const __half* __restrict__ Bh, const float* __restrict__ bias,
               __half* __restrict__ Dh, __half* __restrict__ Dl,
               float* __restrict__ Df) {
    constexpr int BSTR = BNT + 8;
    constexpr int APL  = BMT * ASTR * 2;          // bytes per A plane
    constexpr int BSZ  = BKK * BSTR * 2;          // bytes per B plane
    constexpr int O_AHs = 0;
    constexpr int O_ALs = APL;
    constexpr int O_BHs = 2 * APL;
    constexpr int BUF_BYTES = 2 * APL + BSZ;
    constexpr int NWN  = BNT / 32;                // warps along N
    constexpr int TPRA = NT / BMT;                // threads per A row
    constexpr int ACH  = 32 / (8 * TPRA);         // 16B chunks/plane/thread
    constexpr int TPRB = NT / BKK;                // threads per B row
    constexpr int BCH  = BNT / (8 * TPRB);        // 16B chunks/thread

    const int e = blockIdx.y;
    const int cnt = g_cnt[e];
    const int m0 = blockIdx.z * BMT;
    if (m0 >= cnt) return;
    const int n0 = blockIdx.x * BNT;

    extern __shared__ __align__(16) char dsm[];
    __shared__ int toks_s[BMT];

    const int tid = threadIdx.x;
    const int wid = tid >> 5;
    const int lane = tid & 31;
    const int warp_m = wid / NWN;
    const int warp_n = wid % NWN;

    if (tid < BMT) {
        int m = m0 + tid;
        toks_s[tid] = (m < cnt) ? g_idx[e * T_TOK + m] : -1;
    }
    __syncthreads();

    // loader mapping (invalid rows read token 0; outputs skipped in epilogue)
    const int a_row = tid / TPRA;
    const int a_c   = (tid % TPRA) * ACH;         // 8-half chunk idx within row
    const int tokA  = toks_s[a_row];
    const __half* aSrcH = Ah + (size_t)((tokA >= 0) ? tokA : 0) * A_STRIDE;
    const __half* aSrcL = Al + (size_t)((tokA >= 0) ? tokA : 0) * A_STRIDE;
    const int b_row = tid / TPRB;
    const int b_c   = (tid % TPRB) * BCH;
    const __half* bSrc = Bh + (size_t)e * K_TOTAL * B_STRIDE
                        + (size_t)b_row * B_STRIDE + n0 + b_c * 8;

    const uint32_t a_sts = (uint32_t)((a_row * ASTR + a_c * 8) * 2);
    const uint32_t b_sts = (uint32_t)((b_row * BSTR + b_c * 8) * 2);

    uint4 rah[ACH], ral[ACH], rbv[BCH];
#define LDG_TILE(k0) do { \
    _Pragma("unroll") \
    for (int j = 0; j < ACH; j++) { \
        rah[j] = *(const uint4*)(aSrcH + (k0) + (a_c + j) * 8); \
        ral[j] = *(const uint4*)(aSrcL + (k0) + (a_c + j) * 8); \
    } \
    _Pragma("unroll") \
    for (int j = 0; j < BCH; j++) \
        rbv[j] = *(const uint4*)(bSrc + (size_t)(k0) * B_STRIDE + j * 8); \
} while (0)
#define STS_TILE(base) do { \
    _Pragma("unroll") \
    for (int j = 0; j < ACH; j++) { \
        *(uint4*)((base) + O_AHs + a_sts + j * 16) = rah[j]; \
        *(uint4*)((base) + O_ALs + a_sts + j * 16) = ral[j]; \
    } \
    _Pragma("unroll") \
    for (int j = 0; j < BCH; j++) \
        *(uint4*)((base) + O_BHs + b_sts + j * 16) = rbv[j]; \
} while (0)

    // prologue: iter 0 -> buffer 0, prefetch iter 1
    LDG_TILE(0);
    STS_TILE(dsm);
    if (K_TOTAL > BKK) LDG_TILE(BKK);
    __syncthreads();

    float acc[2][4][4];
#pragma unroll
    for (int mi = 0; mi < 2; mi++)
#pragma unroll
        for (int nj = 0; nj < 4; nj++)
#pragma unroll
            for (int q = 0; q < 4; q++) acc[mi][nj][q] = 0.f;

    const uint32_t dynb = sptr(dsm);
    const int lm  = lane & 15;
    const int lg8 = (lane >> 4) * 8;
    const uint32_t aoff = (uint32_t)(((warp_m * 32 + lm) * ASTR + lg8) * 2);
    const uint32_t boff = (uint32_t)((lm * BSTR + warp_n * 32 + lg8) * 2);

    const int n_iters = K_TOTAL / BKK;
    for (int it = 0; it < n_iters; ++it) {
        const int cur = it & 1;

        // STS iter it+1 into the other buffer (its readers finished last iter)
        if (it + 1 < n_iters) {
            char* nb = dsm + (cur ^ 1) * BUF_BYTES;
            STS_TILE(nb);
        }
        // LDG iter it+2 into registers
        if (it + 2 < n_iters) LDG_TILE((it + 2) * BKK);

        // compute current buffer: 2 x k16 steps, 2-term fp16 split
        const uint32_t sb = dynb + cur * BUF_BYTES;
        const uint32_t aH = sb + O_AHs;
        const uint32_t aL = sb + O_ALs;
        const uint32_t bB = sb + O_BHs;
#pragma unroll
        for (int kk = 0; kk < 2; kk++) {
            uint32_t fah[2][4], fal[2][4], fbh[2][4];
#pragma unroll
            for (int ni = 0; ni < 2; ni++) {
                uint32_t ba = boff + (uint32_t)((kk * 16 * BSTR + ni * 16) * 2);
                LDSM4T(fbh[ni], bB + ba);
            }
#pragma unroll
            for (int mi = 0; mi < 2; mi++) {
                uint32_t aa = aoff + (uint32_t)((mi * 16 * ASTR + kk * 16) * 2);
                LDSM4(fah[mi], aH + aa);
                LDSM4(fal[mi], aL + aa);
            }
#pragma unroll
            for (int mi = 0; mi < 2; mi++) {
#pragma unroll
                for (int nj = 0; nj < 4; nj++) {
                    uint32_t b0 = fbh[nj >> 1][(nj & 1) * 2];
                    uint32_t b1 = fbh[nj >> 1][(nj & 1) * 2 + 1];
                    MMA16816(acc[mi][nj], fah[mi], b0, b1);
                    MMA16816(acc[mi][nj], fal[mi], b0, b1);
                }
            }
        }
        __syncthreads();
    }
#undef LDG_TILE
#undef STS_TILE

    // epilogue: straight from registers
    const int r4 = lane >> 2;
    const int c2 = (lane & 3) * 2;
    const float* bias_p = bias + (size_t)e * B_STRIDE + n0 + warp_n * 32;
#pragma unroll
    for (int mi = 0; mi < 2; mi++) {
#pragma unroll
        for (int half_ = 0; half_ < 2; half_++) {
            int rl = warp_m * 32 + mi * 16 + half_ * 8 + r4;
            int tok = toks_s[rl];
            if (tok < 0) continue;
#pragma unroll
            for (int nj = 0; nj < 4; nj++) {
                int c = nj * 8 + c2;
                float v0 = acc[mi][nj][half_ * 2 + 0] + bias_p[c];
                float v1 = acc[mi][nj][half_ * 2 + 1] + bias_p[c + 1];
                if (FFN1) {
                    v0 = v0 / (1.f + expf(-v0));
                    v1 = v1 / (1.f + expf(-v1));
                    __half h0 = __float2half_rn(v0);
                    __half h1 = __float2half_rn(v1);
                    __half l0 = __float2half_rn(v0 - __half2float(h0));
                    __half l1 = __float2half_rn(v1 - __half2float(h1));
                    size_t o = (size_t)tok * B_STRIDE + n0 + warp_n * 32 + c;
                    *(__half2*)(Dh + o) = __halves2half2(h0, h1);
                    *(__half2*)(Dl + o) = __halves2half2(l0, l1);
                } else {
                    float p = g_prob[tok];
                    float2 o2;
                    o2.x = v0 * p;
                    o2.y = v1 * p;
                    *(float2*)(Df + (size_t)tok * B_STRIDE + n0 + warp_n * 32 + c) = o2;
                }
            }
        }
    }
}

// ---------------------------------------------------------------------------
// FFN1: BM=64, BN=128, 256 threads, MINB=2 (multi-CTA overlap).
// FFN2: BM=64, BN=64, 128 threads, MINB=4.
#define F1_SMEM (2 * (2 * (64 * ASTR * 2) + (BKK * (128 + 8) * 2)))    // 37888
#define F2_SMEM (2 * (2 * (64 * ASTR * 2) + (BKK * (64 + 8) * 2)))     // 29696

extern "C" void kernel_launch(void* const* d_in, const int* in_sizes, int n_in,
                              void* d_out, int out_size) {
    const float* x  = (const float*)d_in[0];
    const float* rw = (const float*)d_in[1];
    const float* rb = (const float*)d_in[2];
    const float* w1 = (const float*)d_in[3];
    const float* b1 = (const float*)d_in[4];
    const float* w2 = (const float*)d_in[5];
    const float* b2 = (const float*)d_in[6];
    float* out = (float*)d_out;

    cudaFuncSetAttribute(
        ffn_mma_kernel<C_DIM, C_DIM, F_DIM, true, 64, 128, 256, 2>,
        cudaFuncAttributeMaxDynamicSharedMemorySize, F1_SMEM);
    cudaFuncSetAttribute(
        ffn_mma_kernel<F_DIM, F_DIM, C_DIM, false, 64, 64, 128, 4>,
        cudaFuncAttributeMaxDynamicSharedMemorySize, F2_SMEM);

    __half *xh, *xl, *w1h, *w2h, *hh, *hl;
    cudaGetSymbolAddress((void**)&xh,  g_xh);
    cudaGetSymbolAddress((void**)&xl,  g_xl);
    cudaGetSymbolAddress((void**)&w1h, g_w1h);
    cudaGetSymbolAddress((void**)&w2h, g_w2h);
    cudaGetSymbolAddress((void**)&hh,  g_hh);
    cudaGetSymbolAddress((void**)&hl,  g_hl);

    init_kernel<<<1, 32>>>();
    // operand prep (streaming, 16B stores)
    const int n8w = E_NUM * C_DIM * F_DIM / 8;
    cvt_w2_kernel<<<4096, 256>>>((const float4*)w1, (const float4*)w2,
                                 (uint4*)w1h, (uint4*)w2h, n8w);
    cvt_split_kernel<<<512, 256>>>((const float4*)x, (uint4*)xh, (uint4*)xl,
                                   T_TOK * C_DIM / 8);
    router_kernel<<<ROUTER_BLOCKS, 256>>>(x, rw, rb);
    aux_kernel<<<1, 256>>>(out, out_size);

    // FFN1: [cnt_e,1024] @ [1024,4096] -> silu -> (g_hh, g_hl)
    ffn_mma_kernel<C_DIM, C_DIM, F_DIM, true, 64, 128, 256, 2>
        <<<dim3(F_DIM / 128, E_NUM, T_TOK / 64), 256, F1_SMEM>>>(
            xh, xl, w1h, b1, hh, hl, nullptr);
    // FFN2: [cnt_e,4096] @ [4096,1024] -> *prob -> out
    ffn_mma_kernel<F_DIM, F_DIM, C_DIM, false, 64, 64, 128, 4>
        <<<dim3(C_DIM / 64, E_NUM, T_TOK / 64), 128, F2_SMEM>>>(
            hh, hl, w2h, b2, nullptr, nullptr, out);
}

// round 16
// speedup vs baseline: 1.4772x; 1.3496x over previous
#include <cuda_runtime.h>
#include <cuda_fp16.h>
#include <math.h>
#include <stdint.h>

// Problem constants
#define T_TOK 2048
#define C_DIM 1024
#define F_DIM 4096
#define E_NUM 8
#define ROUTER_BLOCKS 256   // 8 tokens (warps) per block

// Scratch (allocation-free rule: __device__ globals)
__device__ int   g_cnt[E_NUM];
__device__ int   g_idx[E_NUM * T_TOK];
__device__ float g_prob[T_TOK];
__device__ float g_partial[ROUTER_BLOCKS * E_NUM];
// fp16 operand planes (single plane each)
__device__ __align__(256) __half g_xh[(size_t)T_TOK * C_DIM];
__device__ __align__(256) __half g_w1h[(size_t)E_NUM * C_DIM * F_DIM];
__device__ __align__(256) __half g_w2h[(size_t)E_NUM * F_DIM * C_DIM];
__device__ __align__(256) __half g_hh[(size_t)T_TOK * F_DIM];

// ---------------------------------------------------------------------------
__global__ void init_kernel() {
    int i = threadIdx.x;
    if (i < E_NUM) g_cnt[i] = 0;
}

// Streaming converters: 2x float4 loads -> 1x uint4 (16B) store -------------
__device__ __forceinline__ uint4 pack8_fp16(float4 f0, float4 f1) {
    __half2 a = __floats2half2_rn(f0.x, f0.y);
    __half2 b = __floats2half2_rn(f0.z, f0.w);
    __half2 c = __floats2half2_rn(f1.x, f1.y);
    __half2 d = __floats2half2_rn(f1.z, f1.w);
    return make_uint4(*(uint32_t*)&a, *(uint32_t*)&b,
                      *(uint32_t*)&c, *(uint32_t*)&d);
}

// Converts BOTH weight tensors in one launch. n8 = uint4 outputs per tensor.
__global__ void cvt_w2_kernel(const float4* __restrict__ wa,
                              const float4* __restrict__ wb,
                              uint4* __restrict__ da,
                              uint4* __restrict__ db, int n8) {
    const int stride = gridDim.x * blockDim.x;
    const int i0 = blockIdx.x * blockDim.x + threadIdx.x;
    const int total = 2 * n8;
    for (int base = i0; base < total; base += 2 * stride) {
        float4 f0[2], f1[2];
#pragma unroll
        for (int j = 0; j < 2; j++) {
            int i = base + j * stride;
            if (i < total) {
                const float4* src = (i < n8) ? (wa + 2 * (size_t)i)
                                             : (wb + 2 * (size_t)(i - n8));
                f0[j] = __ldcs(src);
                f1[j] = __ldcs(src + 1);
            }
        }
#pragma unroll
        for (int j = 0; j < 2; j++) {
            int i = base + j * stride;
            if (i < total) {
                uint4 v = pack8_fp16(f0[j], f1[j]);
                if (i < n8) __stcs(&da[i], v);
                else        __stcs(&db[i - n8], v);
            }
        }
    }
}
// x -> fp16 plane; n8 = uint4 outputs.
__global__ void cvt_x_kernel(const float4* __restrict__ x,
                             uint4* __restrict__ xh, int n8) {
    const int stride = gridDim.x * blockDim.x;
    const int i0 = blockIdx.x * blockDim.x + threadIdx.x;
    for (int i = i0; i < n8; i += stride) {
        float4 f0 = __ldcs(x + 2 * (size_t)i);
        float4 f1 = __ldcs(x + 2 * (size_t)i + 1);
        __stcs(&xh[i], pack8_fp16(f0, f1));
    }
}

// ---------------------------------------------------------------------------
// Router: one warp per token. Deterministic importance partials per block.
__global__ void router_kernel(const float* __restrict__ x,
                              const float* __restrict__ rw,
                              const float* __restrict__ rb) {
    int warp = threadIdx.x >> 5;
    int lane = threadIdx.x & 31;
    int t = blockIdx.x * 8 + warp;

    float acc[E_NUM];
#pragma unroll
    for (int e = 0; e < E_NUM; e++) acc[e] = 0.f;

    const float* xr = x + (size_t)t * C_DIM;
    for (int c = lane; c < C_DIM; c += 32) {
        float xv = xr[c];
        const float4* r = (const float4*)(rw + c * E_NUM);
        float4 r0 = r[0];
        float4 r1 = r[1];
        acc[0] += xv * r0.x; acc[1] += xv * r0.y;
        acc[2] += xv * r0.z; acc[3] += xv * r0.w;
        acc[4] += xv * r1.x; acc[5] += xv * r1.y;
        acc[6] += xv * r1.z; acc[7] += xv * r1.w;
    }
#pragma unroll
    for (int e = 0; e < E_NUM; e++) {
#pragma unroll
        for (int o = 16; o > 0; o >>= 1)
            acc[e] += __shfl_xor_sync(0xffffffffu, acc[e], o);
    }

    __shared__ float s_p[8][E_NUM];
    if (lane == 0) {
        float lg[E_NUM];
        float mx = -1e30f; int am = 0;
#pragma unroll
        for (int e = 0; e < E_NUM; e++) {
            lg[e] = acc[e] + rb[e];
            if (lg[e] > mx) { mx = lg[e]; am = e; }
        }
        float s = 0.f, p[E_NUM];
#pragma unroll
        for (int e = 0; e < E_NUM; e++) { p[e] = expf(lg[e] - mx); s += p[e]; }
        float inv = 1.f / s;
#pragma unroll
        for (int e = 0; e < E_NUM; e++) { p[e] *= inv; s_p[warp][e] = p[e]; }
        g_prob[t] = p[am];
        int pos = atomicAdd(&g_cnt[am], 1);
        g_idx[am * T_TOK + pos] = t;
    }
    __syncthreads();
    if (threadIdx.x < E_NUM) {
        int e = threadIdx.x;
        float s = 0.f;
#pragma unroll
        for (int w = 0; w < 8; w++) s += s_p[w][e];
        g_partial[blockIdx.x * E_NUM + e] = s;
    }
}

// ---------------------------------------------------------------------------
// Aux loss: parallel deterministic reduction.
__global__ void aux_kernel(float* __restrict__ out, int out_size) {
    __shared__ float s_e[E_NUM];
    int wid = threadIdx.x >> 5;
    int lane = threadIdx.x & 31;
    if (wid < E_NUM) {
        float s = 0.f;
#pragma unroll
        for (int j = 0; j < ROUTER_BLOCKS / 32; j++)
            s += g_partial[(j * 32 + lane) * E_NUM + wid];
#pragma unroll
        for (int o = 16; o > 0; o >>= 1)
            s += __shfl_xor_sync(0xffffffffu, s, o);
        if (lane == 0) {
            float imp = s * (1.f / (float)T_TOK);
            float load = (float)g_cnt[wid] * (1.f / (float)T_TOK);
            s_e[wid] = imp * load;
        }
    }
    __syncthreads();
    if (threadIdx.x == 0) {
        float a = 0.f;
        for (int e = 0; e < E_NUM; e++) a += s_e[e];
        out[out_size - 1] = (float)E_NUM * a;
    }
}

// ===========================================================================
// Single-plane fp16 GEMM (1 MMA per k16). Warp tile 32x32; BKK=32;
// double-buffered SMEM, one barrier per K-iteration. Plain LDG/STS only.
// ===========================================================================
#define LDSM4(r, a) \
    asm volatile("ldmatrix.sync.aligned.m8n8.x4.shared.b16 {%0,%1,%2,%3}, [%4];" \
        : "=r"((r)[0]), "=r"((r)[1]), "=r"((r)[2]), "=r"((r)[3]) : "r"(a))
#define LDSM4T(r, a) \
    asm volatile("ldmatrix.sync.aligned.m8n8.x4.trans.shared.b16 {%0,%1,%2,%3}, [%4];" \
        : "=r"((r)[0]), "=r"((r)[1]), "=r"((r)[2]), "=r"((r)[3]) : "r"(a))
#define MMA16816(d, a, b0, b1) \
    asm volatile("mma.sync.aligned.m16n8k16.row.col.f32.f16.f16.f32 " \
        "{%0,%1,%2,%3}, {%4,%5,%6,%7}, {%8,%9}, {%0,%1,%2,%3};" \
        : "+f"((d)[0]), "+f"((d)[1]), "+f"((d)[2]), "+f"((d)[3]) \
        : "r"((a)[0]), "r"((a)[1]), "r"((a)[2]), "r"((a)[3]), "r"(b0), "r"(b1))

__device__ __forceinline__ uint32_t sptr(const void* p) {
    return (uint32_t)__cvta_generic_to_shared(p);
}

#define BKK 32
#define ASTR 40     // padded A row (32 + 8 fp16)

// FFN1: D = silu(x @ w1 + b1) -> g_hh; FFN2: D = (h @ w2 + b2)*prob -> Df
template<int K_TOTAL, int A_STRIDE, int B_STRIDE, bool FFN1,
         int BMT, int BNT, int NT, int MINB>
__global__ void __launch_bounds__(NT, MINB)
ffn_mma_kernel(const __half* __restrict__ Ah, const __half* __restrict__ Bh,
               const float* __restrict__ bias,
               __half* __restrict__ Dh, float* __restrict__ Df) {
    constexpr int BSTR = BNT + 8;
    constexpr int APL  = BMT * ASTR * 2;          // bytes, A plane
    constexpr int BSZ  = BKK * BSTR * 2;          // bytes, B plane
    constexpr int O_AHs = 0;
    constexpr int O_BHs = APL;
    constexpr int BUF_BYTES = APL + BSZ;
    constexpr int NWN  = BNT / 32;                // warps along N
    constexpr int TPRA = NT / BMT;                // threads per A row
    constexpr int ACH  = 32 / (8 * TPRA);         // 16B chunks/thread (A)
    constexpr int TPRB = NT / BKK;                // threads per B row
    constexpr int BCH  = BNT / (8 * TPRB);        // 16B chunks/thread (B)

    const int e = blockIdx.y;
    const int cnt = g_cnt[e];
    const int m0 = blockIdx.z * BMT;
    if (m0 >= cnt) return;
    const int n0 = blockIdx.x * BNT;

    extern __shared__ __align__(16) char dsm[];
    __shared__ int toks_s[BMT];

    const int tid = threadIdx.x;
    const int wid = tid >> 5;
    const int lane = tid & 31;
    const int warp_m = wid / NWN;
    const int warp_n = wid % NWN;

    if (tid < BMT) {
        int m = m0 + tid;
        toks_s[tid] = (m < cnt) ? g_idx[e * T_TOK + m] : -1;
    }
    __syncthreads();

    // loader mapping (invalid rows read token 0; outputs skipped in epilogue)
    const int a_row = tid / TPRA;
    const int a_c   = (tid % TPRA) * ACH;
    const int tokA  = toks_s[a_row];
    const __half* aSrcH = Ah + (size_t)((tokA >= 0) ? tokA : 0) * A_STRIDE;
    const int b_row = tid / TPRB;
    const int b_c   = (tid % TPRB) * BCH;
    const __half* bSrc = Bh + (size_t)e * K_TOTAL * B_STRIDE
                        + (size_t)b_row * B_STRIDE + n0 + b_c * 8;

    const uint32_t a_sts = (uint32_t)((a_row * ASTR + a_c * 8) * 2);
    const uint32_t b_sts = (uint32_t)((b_row * BSTR + b_c * 8) * 2);

    uint4 rah[ACH], rbv[BCH];
#define LDG_TILE(k0) do { \
    _Pragma("unroll") \
    for (int j = 0; j < ACH; j++) \
        rah[j] = *(const uint4*)(aSrcH + (k0) + (a_c + j) * 8); \
    _Pragma("unroll") \
    for (int j = 0; j < BCH; j++) \
        rbv[j] = *(const uint4*)(bSrc + (size_t)(k0) * B_STRIDE + j * 8); \
} while (0)
#define STS_TILE(base) do { \
    _Pragma("unroll") \
    for (int j = 0; j < ACH; j++) \
        *(uint4*)((base) + O_AHs + a_sts + j * 16) = rah[j]; \
    _Pragma("unroll") \
    for (int j = 0; j < BCH; j++) \
        *(uint4*)((base) + O_BHs + b_sts + j * 16) = rbv[j]; \
} while (0)

    // prologue: iter 0 -> buffer 0, prefetch iter 1
    LDG_TILE(0);
    STS_TILE(dsm);
    if (K_TOTAL > BKK) LDG_TILE(BKK);
    __syncthreads();

    float acc[2][4][4];
#pragma unroll
    for (int mi = 0; mi < 2; mi++)
#pragma unroll
        for (int nj = 0; nj < 4; nj++)
#pragma unroll
            for (int q = 0; q < 4; q++) acc[mi][nj][q] = 0.f;

    const uint32_t dynb = sptr(dsm);
    const int lm  = lane & 15;
    const int lg8 = (lane >> 4) * 8;
    const uint32_t aoff = (uint32_t)(((warp_m * 32 + lm) * ASTR + lg8) * 2);
    const uint32_t boff = (uint32_t)((lm * BSTR + warp_n * 32 + lg8) * 2);

    const int n_iters = K_TOTAL / BKK;
    for (int it = 0; it < n_iters; ++it) {
        const int cur = it & 1;

        // STS iter it+1 into the other buffer (its readers finished last iter)
        if (it + 1 < n_iters) {
            char* nb = dsm + (cur ^ 1) * BUF_BYTES;
            STS_TILE(nb);
        }
        // LDG iter it+2 into registers
        if (it + 2 < n_iters) LDG_TILE((it + 2) * BKK);

        // compute current buffer: 2 x k16 steps, single fp16 MMA
        const uint32_t sb = dynb + cur * BUF_BYTES;
        const uint32_t aH = sb + O_AHs;
        const uint32_t bB = sb + O_BHs;
#pragma unroll
        for (int kk = 0; kk < 2; kk++) {
            uint32_t fah[2][4], fbh[2][4];
#pragma unroll
            for (int ni = 0; ni < 2; ni++) {
                uint32_t ba = boff + (uint32_t)((kk * 16 * BSTR + ni * 16) * 2);
                LDSM4T(fbh[ni], bB + ba);
            }
#pragma unroll
            for (int mi = 0; mi < 2; mi++) {
                uint32_t aa = aoff + (uint32_t)((mi * 16 * ASTR + kk * 16) * 2);
                LDSM4(fah[mi], aH + aa);
            }
#pragma unroll
            for (int mi = 0; mi < 2; mi++) {
#pragma unroll
                for (int nj = 0; nj < 4; nj++) {
                    uint32_t b0 = fbh[nj >> 1][(nj & 1) * 2];
                    uint32_t b1 = fbh[nj >> 1][(nj & 1) * 2 + 1];
                    MMA16816(acc[mi][nj], fah[mi], b0, b1);
                }
            }
        }
        __syncthreads();
    }
#undef LDG_TILE
#undef STS_TILE

    // epilogue: straight from registers
    const int r4 = lane >> 2;
    const int c2 = (lane & 3) * 2;
    const float* bias_p = bias + (size_t)e * B_STRIDE + n0 + warp_n * 32;
#pragma unroll
    for (int mi = 0; mi < 2; mi++) {
#pragma unroll
        for (int half_ = 0; half_ < 2; half_++) {
            int rl = warp_m * 32 + mi * 16 + half_ * 8 + r4;
            int tok = toks_s[rl];
            if (tok < 0) continue;
#pragma unroll
            for (int nj = 0; nj < 4; nj++) {
                int c = nj * 8 + c2;
                float v0 = acc[mi][nj][half_ * 2 + 0] + bias_p[c];
                float v1 = acc[mi][nj][half_ * 2 + 1] + bias_p[c + 1];
                if (FFN1) {
                    v0 = v0 / (1.f + expf(-v0));
                    v1 = v1 / (1.f + expf(-v1));
                    size_t o = (size_t)tok * B_STRIDE + n0 + warp_n * 32 + c;
                    *(__half2*)(Dh + o) = __floats2half2_rn(v0, v1);
                } else {
                    float p = g_prob[tok];
                    float2 o2;
                    o2.x = v0 * p;
                    o2.y = v1 * p;
                    *(float2*)(Df + (size_t)tok * B_STRIDE + n0 + warp_n * 32 + c) = o2;
                }
            }
        }
    }
}

// ---------------------------------------------------------------------------
// FFN1: BM=64, BN=128, 256 threads, MINB=2. FFN2: BM=64, BN=64, 128 thr, MINB=4.
#define F1_SMEM (2 * ((64 * ASTR * 2) + (BKK * (128 + 8) * 2)))   // 27648
#define F2_SMEM (2 * ((64 * ASTR * 2) + (BKK * (64 + 8) * 2)))    // 19456

extern "C" void kernel_launch(void* const* d_in, const int* in_sizes, int n_in,
                              void* d_out, int out_size) {
    const float* x  = (const float*)d_in[0];
    const float* rw = (const float*)d_in[1];
    const float* rb = (const float*)d_in[2];
    const float* w1 = (const float*)d_in[3];
    const float* b1 = (const float*)d_in[4];
    const float* w2 = (const float*)d_in[5];
    const float* b2 = (const float*)d_in[6];
    float* out = (float*)d_out;

    cudaFuncSetAttribute(
        ffn_mma_kernel<C_DIM, C_DIM, F_DIM, true, 64, 128, 256, 2>,
        cudaFuncAttributeMaxDynamicSharedMemorySize, F1_SMEM);
    cudaFuncSetAttribute(
        ffn_mma_kernel<F_DIM, F_DIM, C_DIM, false, 64, 64, 128, 4>,
        cudaFuncAttributeMaxDynamicSharedMemorySize, F2_SMEM);

    __half *xh, *w1h, *w2h, *hh;
    cudaGetSymbolAddress((void**)&xh,  g_xh);
    cudaGetSymbolAddress((void**)&w1h, g_w1h);
    cudaGetSymbolAddress((void**)&w2h, g_w2h);
    cudaGetSymbolAddress((void**)&hh,  g_hh);

    init_kernel<<<1, 32>>>();
    // operand prep (streaming, 16B stores)
    const int n8w = E_NUM * C_DIM * F_DIM / 8;
    cvt_w2_kernel<<<4096, 256>>>((const float4*)w1, (const float4*)w2,
                                 (uint4*)w1h, (uint4*)w2h, n8w);
    cvt_x_kernel<<<512, 256>>>((const float4*)x, (uint4*)xh,
                               T_TOK * C_DIM / 8);
    router_kernel<<<ROUTER_BLOCKS, 256>>>(x, rw, rb);
    aux_kernel<<<1, 256>>>(out, out_size);

    // FFN1: [cnt_e,1024] @ [1024,4096] -> silu -> g_hh
    ffn_mma_kernel<C_DIM, C_DIM, F_DIM, true, 64, 128, 256, 2>
        <<<dim3(F_DIM / 128, E_NUM, T_TOK / 64), 256, F1_SMEM>>>(
            xh, w1h, b1, hh, nullptr);
    // FFN2: [cnt_e,4096] @ [4096,1024] -> *prob -> out
    ffn_mma_kernel<F_DIM, F_DIM, C_DIM, false, 64, 64, 128, 4>
        <<<dim3(C_DIM / 64, E_NUM, T_TOK / 64), 128, F2_SMEM>>>(
            hh, w2h, b2, nullptr, out);
}